// round 12
// baseline (speedup 1.0000x reference)
#include <cuda_runtime.h>
#include <cstdint>

#define Bsz 16
#define Cch 512
#define HWs 4096
#define Lt  77
#define Dd  768
#define NHh 8
#define HDd 64

// ---------------- scratch (device globals; no allocation allowed) ----------------
__device__ float g_q[(size_t)Bsz * HWs * Cch];     // token-major [b][hw][c] (pre-LN)
__device__ float g_attn[(size_t)Bsz * HWs * Cch];  // attention output, token-major
__device__ float g_k[Bsz * Lt * Cch];              // token-major; LN applied by ln_k_apply
__device__ float g_v[Bsz * Lt * Cch];
__device__ float g_qsum[Bsz * HWs];                // per-token sum / sumsq (atomic acc)
__device__ float g_qsq[Bsz * HWs];
__device__ float g_ksum[Bsz * Lt];
__device__ float g_ksq[Bsz * Lt];

// =====================================================================
// helpers
// =====================================================================
__device__ __forceinline__ void mma8(float* c, const uint32_t* a, const uint32_t* b) {
    asm volatile(
        "mma.sync.aligned.m16n8k8.row.col.f32.tf32.tf32.f32 "
        "{%0,%1,%2,%3}, {%4,%5,%6,%7}, {%8,%9}, {%0,%1,%2,%3};"
        : "+f"(c[0]), "+f"(c[1]), "+f"(c[2]), "+f"(c[3])
        : "r"(a[0]), "r"(a[1]), "r"(a[2]), "r"(a[3]), "r"(b[0]), "r"(b[1]));
}

__device__ __forceinline__ void cp16(uint32_t dst, const void* src) {
    asm volatile("cp.async.cg.shared.global [%0], [%1], 16;" :: "r"(dst), "l"(src));
}
__device__ __forceinline__ void cp16z(uint32_t dst, const void* src, bool pred) {
    int sz = pred ? 16 : 0;
    asm volatile("cp.async.cg.shared.global [%0], [%1], 16, %2;" :: "r"(dst), "l"(src), "r"(sz));
}
__device__ __forceinline__ void cp_commit() { asm volatile("cp.async.commit_group;"); }
__device__ __forceinline__ void cp_wait1() { asm volatile("cp.async.wait_group 1;"); }
__device__ __forceinline__ void cp_wait0() { asm volatile("cp.async.wait_group 0;"); }

#define AS_STR 36      // A smem [128][36] row-major m x k
#define BS_STR 36      // B smem [128][36] row-major n x k
#define AQ_STR 136     // q_proj A smem [32][136] k x m
#define STAGE_A (128 * AS_STR)
#define STAGE_B (128 * BS_STR)
#define STAGE_AQ (32 * AQ_STR)

// compute one k=32 chunk; A row-major [m][k] str 36, B row-major [n][k] str 36
__device__ __forceinline__ void mma_chunk(
    const uint32_t* __restrict__ As, const uint32_t* __restrict__ Bs,
    float cacc[4][4][4], int wm, int wn, int g, int tg)
{
    #pragma unroll
    for (int ks = 0; ks < 4; ks++) {
        uint32_t af[4][4], bf[4][2];
        #pragma unroll
        for (int mt = 0; mt < 4; mt++) {
            int base = (wm * 64 + mt * 16 + g) * AS_STR + ks * 8 + tg;
            af[mt][0] = As[base];
            af[mt][1] = As[base + 8 * AS_STR];
            af[mt][2] = As[base + 4];
            af[mt][3] = As[base + 8 * AS_STR + 4];
        }
        #pragma unroll
        for (int nt = 0; nt < 4; nt++) {
            int bb = (wn * 32 + nt * 8 + g) * BS_STR + ks * 8 + tg;
            bf[nt][0] = Bs[bb];
            bf[nt][1] = Bs[bb + 4];
        }
        #pragma unroll
        for (int mt = 0; mt < 4; mt++)
            #pragma unroll
            for (int nt = 0; nt < 4; nt++)
                mma8(cacc[mt][nt], af[mt], bf[nt]);
    }
}

// compute one k=32 chunk; A k-major [k][m] str 136, B row-major [n][k] str 36
__device__ __forceinline__ void mma_chunk_kmaj(
    const uint32_t* __restrict__ As, const uint32_t* __restrict__ Bs,
    float cacc[4][4][4], int wm, int wn, int g, int tg)
{
    #pragma unroll
    for (int ks = 0; ks < 4; ks++) {
        uint32_t af[4][4], bf[4][2];
        #pragma unroll
        for (int mt = 0; mt < 4; mt++) {
            int m = wm * 64 + mt * 16 + g;
            af[mt][0] = As[(ks * 8 + tg) * AQ_STR + m];
            af[mt][1] = As[(ks * 8 + tg) * AQ_STR + m + 8];
            af[mt][2] = As[(ks * 8 + tg + 4) * AQ_STR + m];
            af[mt][3] = As[(ks * 8 + tg + 4) * AQ_STR + m + 8];
        }
        #pragma unroll
        for (int nt = 0; nt < 4; nt++) {
            int bb = (wn * 32 + nt * 8 + g) * BS_STR + ks * 8 + tg;
            bf[nt][0] = Bs[bb];
            bf[nt][1] = Bs[bb + 4];
        }
        #pragma unroll
        for (int mt = 0; mt < 4; mt++)
            #pragma unroll
            for (int nt = 0; nt < 4; nt++)
                mma8(cacc[mt][nt], af[mt], bf[nt]);
    }
}

// quad-reduce (lanes sharing g, tg=0..3) then atomic accumulate row stats
__device__ __forceinline__ void stat_atomic(float s, float q, int tg, float* sumA, float* sqA) {
    s += __shfl_xor_sync(0xffffffffu, s, 1);
    s += __shfl_xor_sync(0xffffffffu, s, 2);
    q += __shfl_xor_sync(0xffffffffu, q, 1);
    q += __shfl_xor_sync(0xffffffffu, q, 2);
    if (tg == 0) { atomicAdd(sumA, s); atomicAdd(sqA, q); }
}

// =====================================================================
// zero stats accumulators
// =====================================================================
__global__ void zero_stats_kernel() {
    int i = blockIdx.x * 256 + threadIdx.x;
    if (i < Bsz * HWs) { g_qsum[i] = 0.f; g_qsq[i] = 0.f; }
    if (i < Bsz * Lt) { g_ksum[i] = 0.f; g_ksq[i] = 0.f; }
}

// =====================================================================
// KV projection (NT): C[m=token][n=c] = sum_d tf[m][d] * W[n][d] + bias[n]
// M=1232, N=512, K=768. grid (4, 10, 2) z: 0->k (+stats), 1->v.
// =====================================================================
__global__ __launch_bounds__(256, 2) void kv_proj_tc(
    const float* __restrict__ tf,
    const float* __restrict__ wk, const float* __restrict__ bk,
    const float* __restrict__ wv, const float* __restrict__ bv)
{
    const int M = Bsz * Lt;
    const float* W; const float* bias; float* out;
    if (blockIdx.z == 0) { W = wk; bias = bk; out = g_k; }
    else                 { W = wv; bias = bv; out = g_v; }

    extern __shared__ uint32_t dsm[];
    uint32_t* Asm[3] = { dsm, dsm + (STAGE_A + STAGE_B), dsm + 2 * (STAGE_A + STAGE_B) };
    uint32_t* Bsm[3] = { dsm + STAGE_A, dsm + (STAGE_A + STAGE_B) + STAGE_A,
                         dsm + 2 * (STAGE_A + STAGE_B) + STAGE_A };

    const int m0 = blockIdx.y * 128, n0 = blockIdx.x * 128;
    const int tid = threadIdx.x, lane = tid & 31, wid = tid >> 5;
    const int wm = wid & 1, wn = wid >> 1;
    const int g = lane >> 2, tg = lane & 3;
    const int r = tid >> 3, c4 = (tid & 7) << 2;
    float cacc[4][4][4] = {};

    auto load_stage = [&](int st, int k0) {
        #pragma unroll
        for (int u = 0; u < 4; u++) {
            int rr = r + u * 32;
            uint32_t da = __cvta_generic_to_shared(&Asm[st][rr * AS_STR + c4]);
            cp16z(da, tf + (size_t)(m0 + rr) * Dd + k0 + c4, (m0 + rr) < M);
            uint32_t db = __cvta_generic_to_shared(&Bsm[st][rr * BS_STR + c4]);
            cp16(db, W + (size_t)(n0 + rr) * Dd + k0 + c4);
        }
        cp_commit();
    };

    const int NCH = Dd / 32;
    load_stage(0, 0);
    load_stage(1, 32);
    for (int ch = 0; ch < NCH; ch++) {
        if (ch < NCH - 1) cp_wait1(); else cp_wait0();
        __syncthreads();
        if (ch + 2 < NCH) load_stage((ch + 2) % 3, (ch + 2) * 32);
        mma_chunk(Asm[ch % 3], Bsm[ch % 3], cacc, wm, wn, g, tg);
    }

    float s0[4] = {}, q0[4] = {}, s1[4] = {}, q1[4] = {};
    #pragma unroll
    for (int mt = 0; mt < 4; mt++) {
        #pragma unroll
        for (int nt = 0; nt < 4; nt++) {
            int m = m0 + wm * 64 + mt * 16 + g;
            int n = n0 + wn * 32 + nt * 8 + tg * 2;
            float2 bb = *(const float2*)(bias + n);
            float2 r0 = make_float2(cacc[mt][nt][0] + bb.x, cacc[mt][nt][1] + bb.y);
            float2 r1 = make_float2(cacc[mt][nt][2] + bb.x, cacc[mt][nt][3] + bb.y);
            if (m < M) *(float2*)(out + (size_t)m * Cch + n) = r0;
            if (m + 8 < M) *(float2*)(out + (size_t)(m + 8) * Cch + n) = r1;
            s0[mt] += r0.x + r0.y; q0[mt] += r0.x * r0.x + r0.y * r0.y;
            s1[mt] += r1.x + r1.y; q1[mt] += r1.x * r1.x + r1.y * r1.y;
        }
    }
    if (blockIdx.z == 0) {
        #pragma unroll
        for (int mt = 0; mt < 4; mt++) {
            int m = m0 + wm * 64 + mt * 16 + g;
            if (m < M) stat_atomic(s0[mt], q0[mt], tg, &g_ksum[m], &g_ksq[m]);
            if (m + 8 < M) stat_atomic(s1[mt], q1[mt], tg, &g_ksum[m + 8], &g_ksq[m + 8]);
        }
    }
}

// =====================================================================
// Apply K LayerNorm in place (stats from kv_proj). grid (Bsz*Lt), 128 thr.
// =====================================================================
__global__ __launch_bounds__(128) void ln_k_apply(
    const float* __restrict__ g2, const float* __restrict__ b2)
{
    int row = blockIdx.x;
    float m = g_ksum[row] * (1.0f / 512.0f);
    float rs = rsqrtf(g_ksq[row] * (1.0f / 512.0f) - m * m + 1e-5f);
    float* p = g_k + (size_t)row * Cch;
    int t = threadIdx.x;
    float4 v = *(float4*)(p + t * 4);
    float4 gg = *(const float4*)(g2 + t * 4);
    float4 bb = *(const float4*)(b2 + t * 4);
    v.x = (v.x - m) * rs * gg.x + bb.x;
    v.y = (v.y - m) * rs * gg.y + bb.y;
    v.z = (v.z - m) * rs * gg.z + bb.z;
    v.w = (v.w - m) * rs * gg.w + bb.w;
    *(float4*)(p + t * 4) = v;
}

// =====================================================================
// Q projection, token-major output + LN stats:
// C[m=token][n=chan] = sum_c X[c][m] * wq[n][c] + bq[n] + 0.05*pe(n,m)
// M=4096, N=512, K=512. grid (4, 32, 16).
// =====================================================================
__global__ __launch_bounds__(256, 2) void q_proj_tc(
    const float* __restrict__ x, const float* __restrict__ wq, const float* __restrict__ bq)
{
    const int b = blockIdx.z;
    const float* X = x + (size_t)b * Cch * HWs;
    float* out = g_q + (size_t)b * HWs * Cch;

    extern __shared__ uint32_t dsm[];
    uint32_t* Asm[3] = { dsm, dsm + (STAGE_AQ + STAGE_B), dsm + 2 * (STAGE_AQ + STAGE_B) };
    uint32_t* Bsm[3] = { dsm + STAGE_AQ, dsm + (STAGE_AQ + STAGE_B) + STAGE_AQ,
                         dsm + 2 * (STAGE_AQ + STAGE_B) + STAGE_AQ };

    const int m0 = blockIdx.y * 128, n0 = blockIdx.x * 128;
    const int tid = threadIdx.x, lane = tid & 31, wid = tid >> 5;
    const int wm = wid & 1, wn = wid >> 1;
    const int g = lane >> 2, tg = lane & 3;
    const int kk = tid >> 5, mc4 = (tid & 31) << 2;
    const int r = tid >> 3, c4 = (tid & 7) << 2;
    float cacc[4][4][4] = {};

    auto load_stage = [&](int st, int k0) {
        #pragma unroll
        for (int u = 0; u < 4; u++) {
            int kr = kk + u * 8;
            uint32_t da = __cvta_generic_to_shared(&Asm[st][kr * AQ_STR + mc4]);
            cp16(da, X + (size_t)(k0 + kr) * HWs + m0 + mc4);
            int rr = r + u * 32;
            uint32_t db = __cvta_generic_to_shared(&Bsm[st][rr * BS_STR + c4]);
            cp16(db, wq + (size_t)(n0 + rr) * Cch + k0 + c4);
        }
        cp_commit();
    };

    const int NCH = Cch / 32;
    load_stage(0, 0);
    load_stage(1, 32);
    for (int ch = 0; ch < NCH; ch++) {
        if (ch < NCH - 1) cp_wait1(); else cp_wait0();
        __syncthreads();
        if (ch + 2 < NCH) load_stage((ch + 2) % 3, (ch + 2) * 32);
        mma_chunk_kmaj(Asm[ch % 3], Bsm[ch % 3], cacc, wm, wn, g, tg);
    }

    const float pes = 0.05f / 63.0f;
    float s0[4] = {}, q0[4] = {}, s1[4] = {}, q1[4] = {};
    #pragma unroll
    for (int mt = 0; mt < 4; mt++) {
        #pragma unroll
        for (int nt = 0; nt < 4; nt++) {
            int m = m0 + wm * 64 + mt * 16 + g;     // token
            int n = n0 + wn * 32 + nt * 8 + tg * 2; // channel
            float2 bb = *(const float2*)(bq + n);
            bool use_x = n < (Cch / 2);
            float pe0 = pes * (float)(use_x ? (m & 63) : ((m >> 6) & 63));
            float pe1 = pes * (float)(use_x ? ((m + 8) & 63) : (((m + 8) >> 6) & 63));
            float2 r0 = make_float2(cacc[mt][nt][0] + bb.x + pe0, cacc[mt][nt][1] + bb.y + pe0);
            float2 r1 = make_float2(cacc[mt][nt][2] + bb.x + pe1, cacc[mt][nt][3] + bb.y + pe1);
            *(float2*)(out + (size_t)m * Cch + n) = r0;
            *(float2*)(out + (size_t)(m + 8) * Cch + n) = r1;
            s0[mt] += r0.x + r0.y; q0[mt] += r0.x * r0.x + r0.y * r0.y;
            s1[mt] += r1.x + r1.y; q1[mt] += r1.x * r1.x + r1.y * r1.y;
        }
    }
    #pragma unroll
    for (int mt = 0; mt < 4; mt++) {
        int m = m0 + wm * 64 + mt * 16 + g;
        size_t row = (size_t)b * HWs + m;
        stat_atomic(s0[mt], q0[mt], tg, &g_qsum[row], &g_qsq[row]);
        stat_atomic(s1[mt], q1[mt], tg, &g_qsum[row + 8], &g_qsq[row + 8]);
    }
}

// =====================================================================
// Output projection + bias + residual (mma.sync, 3-stage):
// C[m=chan][n=token] = sum_c wo[m][c] * g_attn[n][c] + bo[m] + x[b][m][n]
// M=512, N=4096, K=512. grid (32, 4, 16).
// =====================================================================
__global__ __launch_bounds__(256, 2) void o_proj_tc(
    const float* __restrict__ wo, const float* __restrict__ bo,
    const float* __restrict__ x, float* __restrict__ outp)
{
    const int b = blockIdx.z;
    const float* Bm = g_attn + (size_t)b * HWs * Cch;

    extern __shared__ uint32_t dsm[];
    uint32_t* Asm[3] = { dsm, dsm + (STAGE_A + STAGE_B), dsm + 2 * (STAGE_A + STAGE_B) };
    uint32_t* Bsm[3] = { dsm + STAGE_A, dsm + (STAGE_A + STAGE_B) + STAGE_A,
                         dsm + 2 * (STAGE_A + STAGE_B) + STAGE_A };

    const int m0 = blockIdx.y * 128, n0 = blockIdx.x * 128;
    const int tid = threadIdx.x, lane = tid & 31, wid = tid >> 5;
    const int wm = wid & 1, wn = wid >> 1;
    const int g = lane >> 2, tg = lane & 3;
    const int r = tid >> 3, c4 = (tid & 7) << 2;
    float cacc[4][4][4] = {};

    auto load_stage = [&](int st, int k0) {
        #pragma unroll
        for (int u = 0; u < 4; u++) {
            int rr = r + u * 32;
            uint32_t da = __cvta_generic_to_shared(&Asm[st][rr * AS_STR + c4]);
            cp16(da, wo + (size_t)(m0 + rr) * Cch + k0 + c4);
            uint32_t db = __cvta_generic_to_shared(&Bsm[st][rr * BS_STR + c4]);
            cp16(db, Bm + (size_t)(n0 + rr) * Cch + k0 + c4);
        }
        cp_commit();
    };

    const int NCH = Cch / 32;
    load_stage(0, 0);
    load_stage(1, 32);
    for (int ch = 0; ch < NCH; ch++) {
        if (ch < NCH - 1) cp_wait1(); else cp_wait0();
        __syncthreads();
        if (ch + 2 < NCH) load_stage((ch + 2) % 3, (ch + 2) * 32);
        mma_chunk(Asm[ch % 3], Bsm[ch % 3], cacc, wm, wn, g, tg);
    }

    #pragma unroll
    for (int mt = 0; mt < 4; mt++) {
        #pragma unroll
        for (int nt = 0; nt < 4; nt++) {
            int m = m0 + wm * 64 + mt * 16 + g;     // channel
            int n = n0 + wn * 32 + nt * 8 + tg * 2; // token
            float bo0 = bo[m], bo1 = bo[m + 8];
            size_t i0 = (size_t)b * Cch * HWs + (size_t)m * HWs + n;
            size_t i1 = (size_t)b * Cch * HWs + (size_t)(m + 8) * HWs + n;
            float2 x0 = *(const float2*)(x + i0);
            float2 x1 = *(const float2*)(x + i1);
            float2 r0 = make_float2(cacc[mt][nt][0] + bo0 + x0.x, cacc[mt][nt][1] + bo0 + x0.y);
            float2 r1 = make_float2(cacc[mt][nt][2] + bo1 + x1.x, cacc[mt][nt][3] + bo1 + x1.y);
            *(float2*)(outp + i0) = r0;
            *(float2*)(outp + i1) = r1;
        }
    }
}

// =====================================================================
// Tensor-core attention. LN(Q) fused at load (K pre-normalized).
// P handed from S-phase c-frags to PV a-frags via warp-private smem
// (Qs rows reused; STS.64 pairs + LDS.32, __syncwarp only).
// block = 128 q tokens x head x batch. grid (32, 8, 16), 256 threads.
// =====================================================================
#define QS_STR 84          // holds Q (64 cols) then P (80 cols) per row
#define KS_STR 68
#define VS_STR 68
#define ATTN_SMEM ((128 * QS_STR + 80 * KS_STR + 80 * VS_STR + 128 + 128) * 4)

__global__ __launch_bounds__(256) void attn_tc(
    const float* __restrict__ g1, const float* __restrict__ b1)
{
    extern __shared__ float sm[];
    float* Qs = sm;                         // [128][84]
    float* Ks = Qs + 128 * QS_STR;          // [80][68] rows 77..79 zero
    float* Vs = Ks + 80 * KS_STR;           // [80][68] rows 77..79 zero
    float* qmu = Vs + 80 * VS_STR;          // [128]
    float* qrs = qmu + 128;                 // [128]

    const int tid = threadIdx.x, lane = tid & 31, w = tid >> 5;
    const int g = lane >> 2, tg = lane & 3;
    const int t0 = blockIdx.x * 128, h = blockIdx.y, b = blockIdx.z;

    if (tid < 128) {
        size_t row = (size_t)b * HWs + t0 + tid;
        float s = g_qsum[row], q = g_qsq[row];
        float m = s * (1.0f / 512.0f);
        qmu[tid] = m;
        qrs[tid] = rsqrtf(q * (1.0f / 512.0f) - m * m + 1e-5f);
    }
    __syncthreads();

    // load Q (LN applied)
    const float* qb = g_q + ((size_t)b * HWs + t0) * Cch + h * HDd;
    for (int f = tid; f < 128 * 16; f += 256) {
        int t = f >> 4, dc = (f & 15) << 2;
        float4 v = *(const float4*)(qb + (size_t)t * Cch + dc);
        float4 gg = *(const float4*)(g1 + h * HDd + dc);
        float4 bb = *(const float4*)(b1 + h * HDd + dc);
        float m = qmu[t], r = qrs[t];
        float* d = Qs + t * QS_STR + dc;
        d[0] = (v.x - m) * r * gg.x + bb.x;
        d[1] = (v.y - m) * r * gg.y + bb.y;
        d[2] = (v.z - m) * r * gg.z + bb.z;
        d[3] = (v.w - m) * r * gg.w + bb.w;
    }
    // load K (already LN'd) and V; rows >= Lt zero
    const float* kb = g_k + (size_t)b * Lt * Cch + h * HDd;
    const float* vb = g_v + (size_t)b * Lt * Cch + h * HDd;
    for (int f = tid; f < 80 * 16; f += 256) {
        int l = f >> 4, dc = (f & 15) << 2;
        float* kd = Ks + l * KS_STR + dc;
        float* vd = Vs + l * VS_STR + dc;
        if (l < Lt) {
            float4 k4 = *(const float4*)(kb + (size_t)l * Cch + dc);
            float4 v4 = *(const float4*)(vb + (size_t)l * Cch + dc);
            kd[0] = k4.x; kd[1] = k4.y; kd[2] = k4.z; kd[3] = k4.w;
            vd[0] = v4.x; vd[1] = v4.y; vd[2] = v4.z; vd[3] = v4.w;
        } else {
            kd[0] = kd[1] = kd[2] = kd[3] = 0.f;
            vd[0] = vd[1] = vd[2] = vd[3] = 0.f;
        }
    }
    __syncthreads();

    const uint32_t* Qu = (const uint32_t*)Qs;
    const uint32_t* Ku = (const uint32_t*)Ks;
    const uint32_t* Vu = (const uint32_t*)Vs;

    // ---- S = Q K^T (rows w*16..w*16+15, 10 key tiles)
    float sfr[10][4] = {};
    #pragma unroll
    for (int ks = 0; ks < 8; ks++) {
        uint32_t aq[4];
        int ab = (w * 16 + g) * QS_STR + ks * 8 + tg;
        aq[0] = Qu[ab];
        aq[1] = Qu[ab + 8 * QS_STR];
        aq[2] = Qu[ab + 4];
        aq[3] = Qu[ab + 8 * QS_STR + 4];
        #pragma unroll
        for (int nt = 0; nt < 10; nt++) {
            uint32_t bf[2];
            int bb = (nt * 8 + g) * KS_STR + ks * 8 + tg;
            bf[0] = Ku[bb];
            bf[1] = Ku[bb + 4];
            mma8(sfr[nt], aq, bf);
        }
    }

    // ---- softmax (no max-subtraction; LN-bounded scores)
    float sum0 = 0.f, sum1 = 0.f;
    #pragma unroll
    for (int nt = 0; nt < 10; nt++) {
        int c0 = nt * 8 + tg * 2, c1 = c0 + 1;
        float e00 = (c0 < Lt) ? __expf(sfr[nt][0] * 0.125f) : 0.f;
        float e01 = (c1 < Lt) ? __expf(sfr[nt][1] * 0.125f) : 0.f;
        float e10 = (c0 < Lt) ? __expf(sfr[nt][2] * 0.125f) : 0.f;
        float e11 = (c1 < Lt) ? __expf(sfr[nt][3] * 0.125f) : 0.f;
        sum0 += e00 + e01; sum1 += e10 + e11;
        sfr[nt][0] = e00; sfr[nt][1] = e01; sfr[nt][2] = e10; sfr[nt][3] = e11;
    }
    sum0 += __shfl_xor_sync(0xffffffffu, sum0, 1);
    sum0 += __shfl_xor_sync(0xffffffffu, sum0, 2);
    sum1 += __shfl_xor_sync(0xffffffffu, sum1, 1);
    sum1 += __shfl_xor_sync(0xffffffffu, sum1, 2);
    float inv0 = 1.0f / sum0, inv1 = 1.0f / sum1;

    // ---- hand P to smem: warp-private rows of Qs (Q fully consumed)
    __syncwarp();
    {
        float* prow0 = Qs + (w * 16 + g) * QS_STR;
        float* prow1 = Qs + (w * 16 + g + 8) * QS_STR;
        #pragma unroll
        for (int nt = 0; nt < 10; nt++) {
            int c0 = nt * 8 + tg * 2;
            *(float2*)(prow0 + c0) = make_float2(sfr[nt][0] * inv0, sfr[nt][1] * inv0);
            *(float2*)(prow1 + c0) = make_float2(sfr[nt][2] * inv1, sfr[nt][3] * inv1);
        }
    }
    __syncwarp();

    // ---- O = P V (P a-frags via LDS from warp-private rows)
    float ofr[8][4] = {};
    #pragma unroll
    for (int kt = 0; kt < 10; kt++) {
        uint32_t ap[4];
        int ab = (w * 16 + g) * QS_STR + kt * 8 + tg;
        ap[0] = Qu[ab];
        ap[1] = Qu[ab + 8 * QS_STR];
        ap[2] = Qu[ab + 4];
        ap[3] = Qu[ab + 8 * QS_STR + 4];
        #pragma unroll
        for (int nt = 0; nt < 8; nt++) {
            uint32_t bf[2];
            bf[0] = Vu[(kt * 8 + tg) * VS_STR + nt * 8 + g];
            bf[1] = Vu[(kt * 8 + tg + 4) * VS_STR + nt * 8 + g];
            mma8(ofr[nt], ap, bf);
        }
    }

    float* ob = g_attn + ((size_t)b * HWs + t0 + w * 16) * Cch + h * HDd;
    #pragma unroll
    for (int nt = 0; nt < 8; nt++) {
        int n = nt * 8 + tg * 2;
        float2 r0 = make_float2(ofr[nt][0], ofr[nt][1]);
        float2 r1 = make_float2(ofr[nt][2], ofr[nt][3]);
        *(float2*)(ob + (size_t)g * Cch + n) = r0;
        *(float2*)(ob + (size_t)(g + 8) * Cch + n) = r1;
    }
}

// =====================================================================
extern "C" void kernel_launch(void* const* d_in, const int* in_sizes, int n_in,
                              void* d_out, int out_size)
{
    const float* x  = (const float*)d_in[0];
    const float* tf = (const float*)d_in[1];
    const float* wq = (const float*)d_in[2];
    const float* bq = (const float*)d_in[3];
    const float* wk = (const float*)d_in[4];
    const float* bk = (const float*)d_in[5];
    const float* wv = (const float*)d_in[6];
    const float* bv = (const float*)d_in[7];
    const float* wo = (const float*)d_in[8];
    const float* bo = (const float*)d_in[9];
    const float* g1 = (const float*)d_in[10];
    const float* b1 = (const float*)d_in[11];
    const float* g2 = (const float*)d_in[12];
    const float* b2 = (const float*)d_in[13];
    float* out = (float*)d_out;

    const int gemm_smem = 3 * (STAGE_A + STAGE_B) * 4;
    const int qgemm_smem = 3 * (STAGE_AQ + STAGE_B) * 4;
    cudaFuncSetAttribute(kv_proj_tc, cudaFuncAttributeMaxDynamicSharedMemorySize, gemm_smem);
    cudaFuncSetAttribute(q_proj_tc, cudaFuncAttributeMaxDynamicSharedMemorySize, qgemm_smem);
    cudaFuncSetAttribute(o_proj_tc, cudaFuncAttributeMaxDynamicSharedMemorySize, gemm_smem);
    cudaFuncSetAttribute(attn_tc, cudaFuncAttributeMaxDynamicSharedMemorySize, ATTN_SMEM);

    zero_stats_kernel<<<(Bsz * HWs + 255) / 256, 256>>>();
    kv_proj_tc<<<dim3(4, 10, 2), 256, gemm_smem>>>(tf, wk, bk, wv, bv);
    ln_k_apply<<<Bsz * Lt, 128>>>(g2, b2);
    q_proj_tc<<<dim3(4, 32, 16), 256, qgemm_smem>>>(x, wq, bq);
    attn_tc<<<dim3(32, 8, 16), 256, ATTN_SMEM>>>(g1, b1);
    o_proj_tc<<<dim3(32, 4, 16), 256, gemm_smem>>>(wo, bo, x, out);
}

// round 13
// speedup vs baseline: 1.0223x; 1.0223x over previous
#include <cuda_runtime.h>
#include <cstdint>

#define Bsz 16
#define Cch 512
#define HWs 4096
#define Lt  77
#define Dd  768
#define NHh 8
#define HDd 64

// ---------------- scratch (device globals; no allocation allowed) ----------------
__device__ float g_q[(size_t)Bsz * HWs * Cch];     // token-major [b][hw][c] (pre-LN)
__device__ float g_attn[(size_t)Bsz * HWs * Cch];  // attention output, token-major
__device__ float g_k[Bsz * Lt * Cch];              // token-major; LN applied by ln_k_apply
__device__ float g_v[Bsz * Lt * Cch];
__device__ float g_qsum[Bsz * HWs];                // per-token sum / sumsq (atomic acc)
__device__ float g_qsq[Bsz * HWs];
__device__ float g_ksum[Bsz * Lt];
__device__ float g_ksq[Bsz * Lt];

// =====================================================================
// helpers
// =====================================================================
__device__ __forceinline__ void mma8(float* c, const uint32_t* a, const uint32_t* b) {
    asm volatile(
        "mma.sync.aligned.m16n8k8.row.col.f32.tf32.tf32.f32 "
        "{%0,%1,%2,%3}, {%4,%5,%6,%7}, {%8,%9}, {%0,%1,%2,%3};"
        : "+f"(c[0]), "+f"(c[1]), "+f"(c[2]), "+f"(c[3])
        : "r"(a[0]), "r"(a[1]), "r"(a[2]), "r"(a[3]), "r"(b[0]), "r"(b[1]));
}

__device__ __forceinline__ void cp16(uint32_t dst, const void* src) {
    asm volatile("cp.async.cg.shared.global [%0], [%1], 16;" :: "r"(dst), "l"(src));
}
__device__ __forceinline__ void cp16z(uint32_t dst, const void* src, bool pred) {
    int sz = pred ? 16 : 0;
    asm volatile("cp.async.cg.shared.global [%0], [%1], 16, %2;" :: "r"(dst), "l"(src), "r"(sz));
}
__device__ __forceinline__ void cp_commit() { asm volatile("cp.async.commit_group;"); }
__device__ __forceinline__ void cp_wait1() { asm volatile("cp.async.wait_group 1;"); }
__device__ __forceinline__ void cp_wait0() { asm volatile("cp.async.wait_group 0;"); }

#define AS_STR 36      // A smem row-major m x k
#define BS_STR 36      // B smem row-major n x k
#define AQ_STR 136     // q_proj A smem [32][136] k x m
#define STAGE_A (128 * AS_STR)
#define STAGE_B (128 * BS_STR)
#define STAGE_B2 (256 * BS_STR)
#define STAGE_AQ (32 * AQ_STR)

// ---- 128x128 chunk (kv_proj): A row-major, warp tile 64x32 ----
__device__ __forceinline__ void mma_chunk(
    const uint32_t* __restrict__ As, const uint32_t* __restrict__ Bs,
    float cacc[4][4][4], int wm, int wn, int g, int tg)
{
    #pragma unroll
    for (int ks = 0; ks < 4; ks++) {
        uint32_t af[4][4], bf[4][2];
        #pragma unroll
        for (int mt = 0; mt < 4; mt++) {
            int base = (wm * 64 + mt * 16 + g) * AS_STR + ks * 8 + tg;
            af[mt][0] = As[base];
            af[mt][1] = As[base + 8 * AS_STR];
            af[mt][2] = As[base + 4];
            af[mt][3] = As[base + 8 * AS_STR + 4];
        }
        #pragma unroll
        for (int nt = 0; nt < 4; nt++) {
            int bb = (wn * 32 + nt * 8 + g) * BS_STR + ks * 8 + tg;
            bf[nt][0] = Bs[bb];
            bf[nt][1] = Bs[bb + 4];
        }
        #pragma unroll
        for (int mt = 0; mt < 4; mt++)
            #pragma unroll
            for (int nt = 0; nt < 4; nt++)
                mma8(cacc[mt][nt], af[mt], bf[nt]);
    }
}

// ---- 128x256 chunk: A row-major str 36, warp tile 64x64 (4x8 tiles) ----
__device__ __forceinline__ void mma_chunk256(
    const uint32_t* __restrict__ As, const uint32_t* __restrict__ Bs,
    float cacc[4][8][4], int wm, int wn, int g, int tg)
{
    #pragma unroll
    for (int ks = 0; ks < 4; ks++) {
        uint32_t af[4][4], bf[8][2];
        #pragma unroll
        for (int mt = 0; mt < 4; mt++) {
            int base = (wm * 64 + mt * 16 + g) * AS_STR + ks * 8 + tg;
            af[mt][0] = As[base];
            af[mt][1] = As[base + 8 * AS_STR];
            af[mt][2] = As[base + 4];
            af[mt][3] = As[base + 8 * AS_STR + 4];
        }
        #pragma unroll
        for (int nt = 0; nt < 8; nt++) {
            int bb = (wn * 64 + nt * 8 + g) * BS_STR + ks * 8 + tg;
            bf[nt][0] = Bs[bb];
            bf[nt][1] = Bs[bb + 4];
        }
        #pragma unroll
        for (int mt = 0; mt < 4; mt++)
            #pragma unroll
            for (int nt = 0; nt < 8; nt++)
                mma8(cacc[mt][nt], af[mt], bf[nt]);
    }
}

// ---- 128x256 chunk: A k-major str 136 (q_proj), warp tile 64x64 ----
__device__ __forceinline__ void mma_chunk256_kmaj(
    const uint32_t* __restrict__ As, const uint32_t* __restrict__ Bs,
    float cacc[4][8][4], int wm, int wn, int g, int tg)
{
    #pragma unroll
    for (int ks = 0; ks < 4; ks++) {
        uint32_t af[4][4], bf[8][2];
        #pragma unroll
        for (int mt = 0; mt < 4; mt++) {
            int m = wm * 64 + mt * 16 + g;
            af[mt][0] = As[(ks * 8 + tg) * AQ_STR + m];
            af[mt][1] = As[(ks * 8 + tg) * AQ_STR + m + 8];
            af[mt][2] = As[(ks * 8 + tg + 4) * AQ_STR + m];
            af[mt][3] = As[(ks * 8 + tg + 4) * AQ_STR + m + 8];
        }
        #pragma unroll
        for (int nt = 0; nt < 8; nt++) {
            int bb = (wn * 64 + nt * 8 + g) * BS_STR + ks * 8 + tg;
            bf[nt][0] = Bs[bb];
            bf[nt][1] = Bs[bb + 4];
        }
        #pragma unroll
        for (int mt = 0; mt < 4; mt++)
            #pragma unroll
            for (int nt = 0; nt < 8; nt++)
                mma8(cacc[mt][nt], af[mt], bf[nt]);
    }
}

// quad-reduce (lanes sharing g, tg=0..3) then atomic accumulate row stats
__device__ __forceinline__ void stat_atomic(float s, float q, int tg, float* sumA, float* sqA) {
    s += __shfl_xor_sync(0xffffffffu, s, 1);
    s += __shfl_xor_sync(0xffffffffu, s, 2);
    q += __shfl_xor_sync(0xffffffffu, q, 1);
    q += __shfl_xor_sync(0xffffffffu, q, 2);
    if (tg == 0) { atomicAdd(sumA, s); atomicAdd(sqA, q); }
}

// =====================================================================
// zero stats accumulators
// =====================================================================
__global__ void zero_stats_kernel() {
    int i = blockIdx.x * 256 + threadIdx.x;
    if (i < Bsz * HWs) { g_qsum[i] = 0.f; g_qsq[i] = 0.f; }
    if (i < Bsz * Lt) { g_ksum[i] = 0.f; g_ksq[i] = 0.f; }
}

// =====================================================================
// KV projection (NT): M=1232, N=512, K=768. grid (4, 10, 2). 128x128 tile.
// =====================================================================
__global__ __launch_bounds__(256, 2) void kv_proj_tc(
    const float* __restrict__ tf,
    const float* __restrict__ wk, const float* __restrict__ bk,
    const float* __restrict__ wv, const float* __restrict__ bv)
{
    const int M = Bsz * Lt;
    const float* W; const float* bias; float* out;
    if (blockIdx.z == 0) { W = wk; bias = bk; out = g_k; }
    else                 { W = wv; bias = bv; out = g_v; }

    extern __shared__ uint32_t dsm[];
    uint32_t* Asm[3] = { dsm, dsm + (STAGE_A + STAGE_B), dsm + 2 * (STAGE_A + STAGE_B) };
    uint32_t* Bsm[3] = { dsm + STAGE_A, dsm + (STAGE_A + STAGE_B) + STAGE_A,
                         dsm + 2 * (STAGE_A + STAGE_B) + STAGE_A };

    const int m0 = blockIdx.y * 128, n0 = blockIdx.x * 128;
    const int tid = threadIdx.x, lane = tid & 31, wid = tid >> 5;
    const int wm = wid & 1, wn = wid >> 1;
    const int g = lane >> 2, tg = lane & 3;
    const int r = tid >> 3, c4 = (tid & 7) << 2;
    float cacc[4][4][4] = {};

    auto load_stage = [&](int st, int k0) {
        #pragma unroll
        for (int u = 0; u < 4; u++) {
            int rr = r + u * 32;
            uint32_t da = __cvta_generic_to_shared(&Asm[st][rr * AS_STR + c4]);
            cp16z(da, tf + (size_t)(m0 + rr) * Dd + k0 + c4, (m0 + rr) < M);
            uint32_t db = __cvta_generic_to_shared(&Bsm[st][rr * BS_STR + c4]);
            cp16(db, W + (size_t)(n0 + rr) * Dd + k0 + c4);
        }
        cp_commit();
    };

    const int NCH = Dd / 32;
    load_stage(0, 0);
    load_stage(1, 32);
    for (int ch = 0; ch < NCH; ch++) {
        if (ch < NCH - 1) cp_wait1(); else cp_wait0();
        __syncthreads();
        if (ch + 2 < NCH) load_stage((ch + 2) % 3, (ch + 2) * 32);
        mma_chunk(Asm[ch % 3], Bsm[ch % 3], cacc, wm, wn, g, tg);
    }

    float s0[4] = {}, q0[4] = {}, s1[4] = {}, q1[4] = {};
    #pragma unroll
    for (int mt = 0; mt < 4; mt++) {
        #pragma unroll
        for (int nt = 0; nt < 4; nt++) {
            int m = m0 + wm * 64 + mt * 16 + g;
            int n = n0 + wn * 32 + nt * 8 + tg * 2;
            float2 bb = *(const float2*)(bias + n);
            float2 r0 = make_float2(cacc[mt][nt][0] + bb.x, cacc[mt][nt][1] + bb.y);
            float2 r1 = make_float2(cacc[mt][nt][2] + bb.x, cacc[mt][nt][3] + bb.y);
            if (m < M) *(float2*)(out + (size_t)m * Cch + n) = r0;
            if (m + 8 < M) *(float2*)(out + (size_t)(m + 8) * Cch + n) = r1;
            s0[mt] += r0.x + r0.y; q0[mt] += r0.x * r0.x + r0.y * r0.y;
            s1[mt] += r1.x + r1.y; q1[mt] += r1.x * r1.x + r1.y * r1.y;
        }
    }
    if (blockIdx.z == 0) {
        #pragma unroll
        for (int mt = 0; mt < 4; mt++) {
            int m = m0 + wm * 64 + mt * 16 + g;
            if (m < M) stat_atomic(s0[mt], q0[mt], tg, &g_ksum[m], &g_ksq[m]);
            if (m + 8 < M) stat_atomic(s1[mt], q1[mt], tg, &g_ksum[m + 8], &g_ksq[m + 8]);
        }
    }
}

// =====================================================================
// Apply K LayerNorm in place. grid (Bsz*Lt), 128 thr.
// =====================================================================
__global__ __launch_bounds__(128) void ln_k_apply(
    const float* __restrict__ g2, const float* __restrict__ b2)
{
    int row = blockIdx.x;
    float m = g_ksum[row] * (1.0f / 512.0f);
    float rs = rsqrtf(g_ksq[row] * (1.0f / 512.0f) - m * m + 1e-5f);
    float* p = g_k + (size_t)row * Cch;
    int t = threadIdx.x;
    float4 v = *(float4*)(p + t * 4);
    float4 gg = *(const float4*)(g2 + t * 4);
    float4 bb = *(const float4*)(b2 + t * 4);
    v.x = (v.x - m) * rs * gg.x + bb.x;
    v.y = (v.y - m) * rs * gg.y + bb.y;
    v.z = (v.z - m) * rs * gg.z + bb.z;
    v.w = (v.w - m) * rs * gg.w + bb.w;
    *(float4*)(p + t * 4) = v;
}

// =====================================================================
// Q projection, 128m x 256n tile, warp tile 64x64:
// C[m=token][n=chan] = sum_c X[c][m] * wq[n][c] + bq[n] + 0.05*pe(n,m)
// M=4096, N=512, K=512. grid (2, 32, 16).
// =====================================================================
__global__ __launch_bounds__(256, 1) void q_proj_tc(
    const float* __restrict__ x, const float* __restrict__ wq, const float* __restrict__ bq)
{
    const int b = blockIdx.z;
    const float* X = x + (size_t)b * Cch * HWs;
    float* out = g_q + (size_t)b * HWs * Cch;

    extern __shared__ uint32_t dsm[];
    uint32_t* Asm[3] = { dsm, dsm + (STAGE_AQ + STAGE_B2), dsm + 2 * (STAGE_AQ + STAGE_B2) };
    uint32_t* Bsm[3] = { dsm + STAGE_AQ, dsm + (STAGE_AQ + STAGE_B2) + STAGE_AQ,
                         dsm + 2 * (STAGE_AQ + STAGE_B2) + STAGE_AQ };

    const int m0 = blockIdx.y * 128, n0 = blockIdx.x * 256;
    const int tid = threadIdx.x, lane = tid & 31, wid = tid >> 5;
    const int wm = wid & 1, wn = wid >> 1;
    const int g = lane >> 2, tg = lane & 3;
    const int kk = tid >> 5, mc4 = (tid & 31) << 2;
    const int r = tid >> 3, c4 = (tid & 7) << 2;
    float cacc[4][8][4] = {};

    auto load_stage = [&](int st, int k0) {
        #pragma unroll
        for (int u = 0; u < 4; u++) {
            int kr = kk + u * 8;
            uint32_t da = __cvta_generic_to_shared(&Asm[st][kr * AQ_STR + mc4]);
            cp16(da, X + (size_t)(k0 + kr) * HWs + m0 + mc4);
        }
        #pragma unroll
        for (int u = 0; u < 8; u++) {
            int rr = r + u * 32;
            uint32_t db = __cvta_generic_to_shared(&Bsm[st][rr * BS_STR + c4]);
            cp16(db, wq + (size_t)(n0 + rr) * Cch + k0 + c4);
        }
        cp_commit();
    };

    const int NCH = Cch / 32;
    load_stage(0, 0);
    load_stage(1, 32);
    for (int ch = 0; ch < NCH; ch++) {
        if (ch < NCH - 1) cp_wait1(); else cp_wait0();
        __syncthreads();
        if (ch + 2 < NCH) load_stage((ch + 2) % 3, (ch + 2) * 32);
        mma_chunk256_kmaj(Asm[ch % 3], Bsm[ch % 3], cacc, wm, wn, g, tg);
    }

    const float pes = 0.05f / 63.0f;
    float s0[4] = {}, q0[4] = {}, s1[4] = {}, q1[4] = {};
    #pragma unroll
    for (int mt = 0; mt < 4; mt++) {
        int m = m0 + wm * 64 + mt * 16 + g;
        float pw0x = pes * (float)(m & 63), pw0y = pes * (float)((m >> 6) & 63);
        float pw1x = pes * (float)((m + 8) & 63), pw1y = pes * (float)(((m + 8) >> 6) & 63);
        #pragma unroll
        for (int nt = 0; nt < 8; nt++) {
            int n = n0 + wn * 64 + nt * 8 + tg * 2; // channel
            float2 bb = *(const float2*)(bq + n);
            bool use_x = n < (Cch / 2);
            float pe0 = use_x ? pw0x : pw0y;
            float pe1 = use_x ? pw1x : pw1y;
            float2 r0 = make_float2(cacc[mt][nt][0] + bb.x + pe0, cacc[mt][nt][1] + bb.y + pe0);
            float2 r1 = make_float2(cacc[mt][nt][2] + bb.x + pe1, cacc[mt][nt][3] + bb.y + pe1);
            *(float2*)(out + (size_t)m * Cch + n) = r0;
            *(float2*)(out + (size_t)(m + 8) * Cch + n) = r1;
            s0[mt] += r0.x + r0.y; q0[mt] += r0.x * r0.x + r0.y * r0.y;
            s1[mt] += r1.x + r1.y; q1[mt] += r1.x * r1.x + r1.y * r1.y;
        }
    }
    #pragma unroll
    for (int mt = 0; mt < 4; mt++) {
        int m = m0 + wm * 64 + mt * 16 + g;
        size_t row = (size_t)b * HWs + m;
        stat_atomic(s0[mt], q0[mt], tg, &g_qsum[row], &g_qsq[row]);
        stat_atomic(s1[mt], q1[mt], tg, &g_qsum[row + 8], &g_qsq[row + 8]);
    }
}

// =====================================================================
// Output projection + bias + residual, 128m x 256n tile, warp tile 64x64:
// C[m=chan][n=token] = sum_c wo[m][c] * g_attn[n][c] + bo[m] + x[b][m][n]
// M=512, N=4096, K=512. grid (16, 4, 16).
// =====================================================================
__global__ __launch_bounds__(256, 1) void o_proj_tc(
    const float* __restrict__ wo, const float* __restrict__ bo,
    const float* __restrict__ x, float* __restrict__ outp)
{
    const int b = blockIdx.z;
    const float* Bm = g_attn + (size_t)b * HWs * Cch;

    extern __shared__ uint32_t dsm[];
    uint32_t* Asm[3] = { dsm, dsm + (STAGE_A + STAGE_B2), dsm + 2 * (STAGE_A + STAGE_B2) };
    uint32_t* Bsm[3] = { dsm + STAGE_A, dsm + (STAGE_A + STAGE_B2) + STAGE_A,
                         dsm + 2 * (STAGE_A + STAGE_B2) + STAGE_A };

    const int m0 = blockIdx.y * 128, n0 = blockIdx.x * 256;
    const int tid = threadIdx.x, lane = tid & 31, wid = tid >> 5;
    const int wm = wid & 1, wn = wid >> 1;
    const int g = lane >> 2, tg = lane & 3;
    const int r = tid >> 3, c4 = (tid & 7) << 2;
    float cacc[4][8][4] = {};

    auto load_stage = [&](int st, int k0) {
        #pragma unroll
        for (int u = 0; u < 4; u++) {
            int rr = r + u * 32;
            uint32_t da = __cvta_generic_to_shared(&Asm[st][rr * AS_STR + c4]);
            cp16(da, wo + (size_t)(m0 + rr) * Cch + k0 + c4);
        }
        #pragma unroll
        for (int u = 0; u < 8; u++) {
            int rr = r + u * 32;
            uint32_t db = __cvta_generic_to_shared(&Bsm[st][rr * BS_STR + c4]);
            cp16(db, Bm + (size_t)(n0 + rr) * Cch + k0 + c4);
        }
        cp_commit();
    };

    const int NCH = Cch / 32;
    load_stage(0, 0);
    load_stage(1, 32);
    for (int ch = 0; ch < NCH; ch++) {
        if (ch < NCH - 1) cp_wait1(); else cp_wait0();
        __syncthreads();
        if (ch + 2 < NCH) load_stage((ch + 2) % 3, (ch + 2) * 32);
        mma_chunk256(Asm[ch % 3], Bsm[ch % 3], cacc, wm, wn, g, tg);
    }

    #pragma unroll
    for (int mt = 0; mt < 4; mt++) {
        int m = m0 + wm * 64 + mt * 16 + g;     // channel
        float bo0 = bo[m], bo1 = bo[m + 8];
        #pragma unroll
        for (int nt = 0; nt < 8; nt++) {
            int n = n0 + wn * 64 + nt * 8 + tg * 2; // token
            size_t i0 = (size_t)b * Cch * HWs + (size_t)m * HWs + n;
            size_t i1 = (size_t)b * Cch * HWs + (size_t)(m + 8) * HWs + n;
            float2 x0 = *(const float2*)(x + i0);
            float2 x1 = *(const float2*)(x + i1);
            float2 r0 = make_float2(cacc[mt][nt][0] + bo0 + x0.x, cacc[mt][nt][1] + bo0 + x0.y);
            float2 r1 = make_float2(cacc[mt][nt][2] + bo1 + x1.x, cacc[mt][nt][3] + bo1 + x1.y);
            *(float2*)(outp + i0) = r0;
            *(float2*)(outp + i1) = r1;
        }
    }
}

// =====================================================================
// Tensor-core attention (R12 version, unchanged).
// =====================================================================
#define QS_STR 84
#define KS_STR 68
#define VS_STR 68
#define ATTN_SMEM ((128 * QS_STR + 80 * KS_STR + 80 * VS_STR + 128 + 128) * 4)

__global__ __launch_bounds__(256) void attn_tc(
    const float* __restrict__ g1, const float* __restrict__ b1)
{
    extern __shared__ float sm[];
    float* Qs = sm;
    float* Ks = Qs + 128 * QS_STR;
    float* Vs = Ks + 80 * KS_STR;
    float* qmu = Vs + 80 * VS_STR;
    float* qrs = qmu + 128;

    const int tid = threadIdx.x, lane = tid & 31, w = tid >> 5;
    const int g = lane >> 2, tg = lane & 3;
    const int t0 = blockIdx.x * 128, h = blockIdx.y, b = blockIdx.z;

    if (tid < 128) {
        size_t row = (size_t)b * HWs + t0 + tid;
        float s = g_qsum[row], q = g_qsq[row];
        float m = s * (1.0f / 512.0f);
        qmu[tid] = m;
        qrs[tid] = rsqrtf(q * (1.0f / 512.0f) - m * m + 1e-5f);
    }
    __syncthreads();

    const float* qb = g_q + ((size_t)b * HWs + t0) * Cch + h * HDd;
    for (int f = tid; f < 128 * 16; f += 256) {
        int t = f >> 4, dc = (f & 15) << 2;
        float4 v = *(const float4*)(qb + (size_t)t * Cch + dc);
        float4 gg = *(const float4*)(g1 + h * HDd + dc);
        float4 bb = *(const float4*)(b1 + h * HDd + dc);
        float m = qmu[t], r = qrs[t];
        float* d = Qs + t * QS_STR + dc;
        d[0] = (v.x - m) * r * gg.x + bb.x;
        d[1] = (v.y - m) * r * gg.y + bb.y;
        d[2] = (v.z - m) * r * gg.z + bb.z;
        d[3] = (v.w - m) * r * gg.w + bb.w;
    }
    const float* kb = g_k + (size_t)b * Lt * Cch + h * HDd;
    const float* vb = g_v + (size_t)b * Lt * Cch + h * HDd;
    for (int f = tid; f < 80 * 16; f += 256) {
        int l = f >> 4, dc = (f & 15) << 2;
        float* kd = Ks + l * KS_STR + dc;
        float* vd = Vs + l * VS_STR + dc;
        if (l < Lt) {
            float4 k4 = *(const float4*)(kb + (size_t)l * Cch + dc);
            float4 v4 = *(const float4*)(vb + (size_t)l * Cch + dc);
            kd[0] = k4.x; kd[1] = k4.y; kd[2] = k4.z; kd[3] = k4.w;
            vd[0] = v4.x; vd[1] = v4.y; vd[2] = v4.z; vd[3] = v4.w;
        } else {
            kd[0] = kd[1] = kd[2] = kd[3] = 0.f;
            vd[0] = vd[1] = vd[2] = vd[3] = 0.f;
        }
    }
    __syncthreads();

    const uint32_t* Qu = (const uint32_t*)Qs;
    const uint32_t* Ku = (const uint32_t*)Ks;
    const uint32_t* Vu = (const uint32_t*)Vs;

    float sfr[10][4] = {};
    #pragma unroll
    for (int ks = 0; ks < 8; ks++) {
        uint32_t aq[4];
        int ab = (w * 16 + g) * QS_STR + ks * 8 + tg;
        aq[0] = Qu[ab];
        aq[1] = Qu[ab + 8 * QS_STR];
        aq[2] = Qu[ab + 4];
        aq[3] = Qu[ab + 8 * QS_STR + 4];
        #pragma unroll
        for (int nt = 0; nt < 10; nt++) {
            uint32_t bf[2];
            int bb = (nt * 8 + g) * KS_STR + ks * 8 + tg;
            bf[0] = Ku[bb];
            bf[1] = Ku[bb + 4];
            mma8(sfr[nt], aq, bf);
        }
    }

    float sum0 = 0.f, sum1 = 0.f;
    #pragma unroll
    for (int nt = 0; nt < 10; nt++) {
        int c0 = nt * 8 + tg * 2, c1 = c0 + 1;
        float e00 = (c0 < Lt) ? __expf(sfr[nt][0] * 0.125f) : 0.f;
        float e01 = (c1 < Lt) ? __expf(sfr[nt][1] * 0.125f) : 0.f;
        float e10 = (c0 < Lt) ? __expf(sfr[nt][2] * 0.125f) : 0.f;
        float e11 = (c1 < Lt) ? __expf(sfr[nt][3] * 0.125f) : 0.f;
        sum0 += e00 + e01; sum1 += e10 + e11;
        sfr[nt][0] = e00; sfr[nt][1] = e01; sfr[nt][2] = e10; sfr[nt][3] = e11;
    }
    sum0 += __shfl_xor_sync(0xffffffffu, sum0, 1);
    sum0 += __shfl_xor_sync(0xffffffffu, sum0, 2);
    sum1 += __shfl_xor_sync(0xffffffffu, sum1, 1);
    sum1 += __shfl_xor_sync(0xffffffffu, sum1, 2);
    float inv0 = 1.0f / sum0, inv1 = 1.0f / sum1;

    __syncwarp();
    {
        float* prow0 = Qs + (w * 16 + g) * QS_STR;
        float* prow1 = Qs + (w * 16 + g + 8) * QS_STR;
        #pragma unroll
        for (int nt = 0; nt < 10; nt++) {
            int c0 = nt * 8 + tg * 2;
            *(float2*)(prow0 + c0) = make_float2(sfr[nt][0] * inv0, sfr[nt][1] * inv0);
            *(float2*)(prow1 + c0) = make_float2(sfr[nt][2] * inv1, sfr[nt][3] * inv1);
        }
    }
    __syncwarp();

    float ofr[8][4] = {};
    #pragma unroll
    for (int kt = 0; kt < 10; kt++) {
        uint32_t ap[4];
        int ab = (w * 16 + g) * QS_STR + kt * 8 + tg;
        ap[0] = Qu[ab];
        ap[1] = Qu[ab + 8 * QS_STR];
        ap[2] = Qu[ab + 4];
        ap[3] = Qu[ab + 8 * QS_STR + 4];
        #pragma unroll
        for (int nt = 0; nt < 8; nt++) {
            uint32_t bf[2];
            bf[0] = Vu[(kt * 8 + tg) * VS_STR + nt * 8 + g];
            bf[1] = Vu[(kt * 8 + tg + 4) * VS_STR + nt * 8 + g];
            mma8(ofr[nt], ap, bf);
        }
    }

    float* ob = g_attn + ((size_t)b * HWs + t0 + w * 16) * Cch + h * HDd;
    #pragma unroll
    for (int nt = 0; nt < 8; nt++) {
        int n = nt * 8 + tg * 2;
        float2 r0 = make_float2(ofr[nt][0], ofr[nt][1]);
        float2 r1 = make_float2(ofr[nt][2], ofr[nt][3]);
        *(float2*)(ob + (size_t)g * Cch + n) = r0;
        *(float2*)(ob + (size_t)(g + 8) * Cch + n) = r1;
    }
}

// =====================================================================
extern "C" void kernel_launch(void* const* d_in, const int* in_sizes, int n_in,
                              void* d_out, int out_size)
{
    const float* x  = (const float*)d_in[0];
    const float* tf = (const float*)d_in[1];
    const float* wq = (const float*)d_in[2];
    const float* bq = (const float*)d_in[3];
    const float* wk = (const float*)d_in[4];
    const float* bk = (const float*)d_in[5];
    const float* wv = (const float*)d_in[6];
    const float* bv = (const float*)d_in[7];
    const float* wo = (const float*)d_in[8];
    const float* bo = (const float*)d_in[9];
    const float* g1 = (const float*)d_in[10];
    const float* b1 = (const float*)d_in[11];
    const float* g2 = (const float*)d_in[12];
    const float* b2 = (const float*)d_in[13];
    float* out = (float*)d_out;

    const int kv_smem = 3 * (STAGE_A + STAGE_B) * 4;        // 110592 B
    const int q_smem  = 3 * (STAGE_AQ + STAGE_B2) * 4;      // 162816 B
    const int o_smem  = 3 * (STAGE_A + STAGE_B2) * 4;       // 165888 B
    cudaFuncSetAttribute(kv_proj_tc, cudaFuncAttributeMaxDynamicSharedMemorySize, kv_smem);
    cudaFuncSetAttribute(q_proj_tc, cudaFuncAttributeMaxDynamicSharedMemorySize, q_smem);
    cudaFuncSetAttribute(o_proj_tc, cudaFuncAttributeMaxDynamicSharedMemorySize, o_smem);
    cudaFuncSetAttribute(attn_tc, cudaFuncAttributeMaxDynamicSharedMemorySize, ATTN_SMEM);

    zero_stats_kernel<<<(Bsz * HWs + 255) / 256, 256>>>();
    kv_proj_tc<<<dim3(4, 10, 2), 256, kv_smem>>>(tf, wk, bk, wv, bv);
    ln_k_apply<<<Bsz * Lt, 128>>>(g2, b2);
    q_proj_tc<<<dim3(2, 32, 16), 256, q_smem>>>(x, wq, bq);
    attn_tc<<<dim3(32, 8, 16), 256, ATTN_SMEM>>>(g1, b1);
    o_proj_tc<<<dim3(16, 4, 16), 256, o_smem>>>(wo, bo, x, out);
}

// round 15
// speedup vs baseline: 1.2435x; 1.2164x over previous
#include <cuda_runtime.h>
#include <cuda_fp16.h>
#include <cstdint>

#define Bsz 16
#define Cch 512
#define HWs 4096
#define Lt  77
#define Dd  768
#define NHh 8
#define HDd 64

// ---------------- scratch (device globals; no allocation allowed) ----------------
__device__ float g_q[(size_t)Bsz * HWs * Cch];       // token-major [b][hw][c] (pre-LN)
__device__ float g_k[Bsz * Lt * Cch];                // token-major; LN applied by ln_k_apply
__device__ float g_v[Bsz * Lt * Cch];
__device__ float g_qsum[Bsz * HWs];
__device__ float g_qsq[Bsz * HWs];
__device__ float g_ksum[Bsz * Lt];
__device__ float g_ksq[Bsz * Lt];
// half-precision operands
__device__ __half g_xth[(size_t)Bsz * HWs * Cch];    // x transposed: [b][hw][c]
__device__ __half g_attnh[(size_t)Bsz * HWs * Cch];  // attention out (half), token-major
__device__ __half g_wqh[Cch * Cch];
__device__ __half g_wkh[Cch * Dd];
__device__ __half g_wvh[Cch * Dd];
__device__ __half g_woh[Cch * Cch];
__device__ __half g_tfh[Bsz * Lt * Dd];

// =====================================================================
// helpers
// =====================================================================
__device__ __forceinline__ void mma16(float* c, const uint32_t* a, const uint32_t* b) {
    asm volatile(
        "mma.sync.aligned.m16n8k16.row.col.f32.f16.f16.f32 "
        "{%0,%1,%2,%3}, {%4,%5,%6,%7}, {%8,%9}, {%0,%1,%2,%3};"
        : "+f"(c[0]), "+f"(c[1]), "+f"(c[2]), "+f"(c[3])
        : "r"(a[0]), "r"(a[1]), "r"(a[2]), "r"(a[3]), "r"(b[0]), "r"(b[1]));
}
__device__ __forceinline__ void mma8(float* c, const uint32_t* a, const uint32_t* b) {
    asm volatile(
        "mma.sync.aligned.m16n8k8.row.col.f32.tf32.tf32.f32 "
        "{%0,%1,%2,%3}, {%4,%5,%6,%7}, {%8,%9}, {%0,%1,%2,%3};"
        : "+f"(c[0]), "+f"(c[1]), "+f"(c[2]), "+f"(c[3])
        : "r"(a[0]), "r"(a[1]), "r"(a[2]), "r"(a[3]), "r"(b[0]), "r"(b[1]));
}

__device__ __forceinline__ void cp16(uint32_t dst, const void* src) {
    asm volatile("cp.async.cg.shared.global [%0], [%1], 16;" :: "r"(dst), "l"(src));
}
__device__ __forceinline__ void cp16z(uint32_t dst, const void* src, bool pred) {
    int sz = pred ? 16 : 0;
    asm volatile("cp.async.cg.shared.global [%0], [%1], 16, %2;" :: "r"(dst), "l"(src), "r"(sz));
}
__device__ __forceinline__ void cp_commit() { asm volatile("cp.async.commit_group;"); }
__device__ __forceinline__ void cp_wait1() { asm volatile("cp.async.wait_group 1;"); }
__device__ __forceinline__ void cp_wait0() { asm volatile("cp.async.wait_group 0;"); }

// half-GEMM smem: rows of 32 halfs at stride 56 halfs (112 B: 16B-aligned,
// frag banks 28g+tg mod 32 all-distinct -> conflict-free)
#define HS_STR 28                 // stride in u32 (56 halfs)
#define STAGE_AH (128 * HS_STR)   // u32 count
#define STAGE_BH (256 * HS_STR)

// ---- fp16 chunk: 128x256 tile, warp 64x64 (4m x 8n tiles), k-chunk 32 ----
__device__ __forceinline__ void mma_chunk_h(
    const uint32_t* __restrict__ As, const uint32_t* __restrict__ Bs,
    float cacc[4][8][4], int wm, int wn, int g, int tg)
{
    #pragma unroll
    for (int ks = 0; ks < 2; ks++) {
        uint32_t af[4][4], bf[8][2];
        #pragma unroll
        for (int mt = 0; mt < 4; mt++) {
            int base = (wm * 64 + mt * 16 + g) * HS_STR + ks * 8 + tg;
            af[mt][0] = As[base];
            af[mt][1] = As[base + 8 * HS_STR];
            af[mt][2] = As[base + 4];
            af[mt][3] = As[base + 8 * HS_STR + 4];
        }
        #pragma unroll
        for (int nt = 0; nt < 8; nt++) {
            int bb = (wn * 64 + nt * 8 + g) * HS_STR + ks * 8 + tg;
            bf[nt][0] = Bs[bb];
            bf[nt][1] = Bs[bb + 4];
        }
        #pragma unroll
        for (int mt = 0; mt < 4; mt++)
            #pragma unroll
            for (int nt = 0; nt < 8; nt++)
                mma16(cacc[mt][nt], af[mt], bf[nt]);
    }
}

// quad-reduce then atomic accumulate row stats
__device__ __forceinline__ void stat_atomic(float s, float q, int tg, float* sumA, float* sqA) {
    s += __shfl_xor_sync(0xffffffffu, s, 1);
    s += __shfl_xor_sync(0xffffffffu, s, 2);
    q += __shfl_xor_sync(0xffffffffu, q, 1);
    q += __shfl_xor_sync(0xffffffffu, q, 2);
    if (tg == 0) { atomicAdd(sumA, s); atomicAdd(sqA, q); }
}

// =====================================================================
// zero stats
// =====================================================================
__global__ void zero_stats_kernel() {
    int i = blockIdx.x * 256 + threadIdx.x;
    if (i < Bsz * HWs) { g_qsum[i] = 0.f; g_qsq[i] = 0.f; }
    if (i < Bsz * Lt) { g_ksum[i] = 0.f; g_ksq[i] = 0.f; }
}

// =====================================================================
// convert params (weights + text features) fp32 -> fp16, float4-vectorized
// =====================================================================
#define NQ_WQ (Cch * Cch / 4)
#define NQ_WK (Cch * Dd / 4)
#define NQ_WO (Cch * Cch / 4)
#define NQ_TF (Bsz * Lt * Dd / 4)
#define NQ_TOTAL (NQ_WQ + NQ_WK + NQ_WK + NQ_WO + NQ_TF)

__global__ __launch_bounds__(256) void convert_params_kernel(
    const float* __restrict__ wq, const float* __restrict__ wk,
    const float* __restrict__ wv, const float* __restrict__ wo,
    const float* __restrict__ tf)
{
    int idx = blockIdx.x * 256 + threadIdx.x;
    if (idx >= NQ_TOTAL) return;
    const float* src; __half* dst;
    if (idx < NQ_WQ) { src = wq; dst = g_wqh; }
    else if ((idx -= NQ_WQ) < NQ_WK) { src = wk; dst = g_wkh; }
    else if ((idx -= NQ_WK) < NQ_WK) { src = wv; dst = g_wvh; }
    else if ((idx -= NQ_WK) < NQ_WO) { src = wo; dst = g_woh; }
    else { idx -= NQ_WO; src = tf; dst = g_tfh; }
    float4 v = *(const float4*)(src + (size_t)idx * 4);
    __half2 h0 = __floats2half2_rn(v.x, v.y);
    __half2 h1 = __floats2half2_rn(v.z, v.w);
    *(__half2*)(dst + (size_t)idx * 4) = h0;
    *(__half2*)(dst + (size_t)idx * 4 + 2) = h1;
}

// =====================================================================
// transpose-convert x: [b][c][hw] f32 -> g_xth [b][hw][c] half
// tile 32(c) x 32(hw), block 256. grid (HWs/32, Cch/32, Bsz)
// =====================================================================
__global__ __launch_bounds__(256) void xpose_kernel(const float* __restrict__ x)
{
    __shared__ float ts[32][33];
    const int hw0 = blockIdx.x * 32, c0 = blockIdx.y * 32, b = blockIdx.z;
    const int tx = threadIdx.x & 31, ty = threadIdx.x >> 5;   // ty 0..7
    const float* xb = x + (size_t)b * Cch * HWs;
    #pragma unroll
    for (int i = 0; i < 4; i++) {
        int c = ty * 4 + i;
        ts[c][tx] = xb[(size_t)(c0 + c) * HWs + hw0 + tx];
    }
    __syncthreads();
    __half* ob = g_xth + (size_t)b * HWs * Cch;
    const int tx2 = threadIdx.x & 15, tr = threadIdx.x >> 4;  // tr 0..15
    #pragma unroll
    for (int i = 0; i < 2; i++) {
        int r = tr + i * 16;     // hw row within tile
        __half2 h = __floats2half2_rn(ts[tx2 * 2][r], ts[tx2 * 2 + 1][r]);
        *(__half2*)(ob + (size_t)(hw0 + r) * Cch + c0 + tx2 * 2) = h;
    }
}

// =====================================================================
// generic fp16 NT GEMM body: C[128m x 256n] = A[m][k] * B[n][k]^T
// 3-stage cp.async, 256 threads, warp tile 64x64.
// =====================================================================
#define GEMM_SMEM (3 * (STAGE_AH + STAGE_BH) * 4)

// ---- KV projection: M=1232, N=512, K=768. grid (2, 10, 2). ----
__global__ __launch_bounds__(256, 1) void kv_proj_h(
    const float* __restrict__ bk, const float* __restrict__ bv)
{
    const int M = Bsz * Lt;
    const __half* A = g_tfh;
    const __half* Bm; const float* bias; float* out;
    if (blockIdx.z == 0) { Bm = g_wkh; bias = bk; out = g_k; }
    else                 { Bm = g_wvh; bias = bv; out = g_v; }

    extern __shared__ uint32_t dsm[];
    uint32_t* Asm[3] = { dsm, dsm + (STAGE_AH + STAGE_BH), dsm + 2 * (STAGE_AH + STAGE_BH) };
    uint32_t* Bsm[3] = { dsm + STAGE_AH, dsm + (STAGE_AH + STAGE_BH) + STAGE_AH,
                         dsm + 2 * (STAGE_AH + STAGE_BH) + STAGE_AH };

    const int m0 = blockIdx.y * 128, n0 = blockIdx.x * 256;
    const int tid = threadIdx.x, lane = tid & 31, wid = tid >> 5;
    const int wm = wid & 1, wn = wid >> 1;
    const int g = lane >> 2, tg = lane & 3;
    const int r = tid >> 2, kc = (tid & 3) * 8;    // 64 rows per pass, 8-half columns
    float cacc[4][8][4] = {};

    auto load_stage = [&](int st, int k0) {
        #pragma unroll
        for (int u = 0; u < 2; u++) {
            int rr = r + u * 64;
            uint32_t da = __cvta_generic_to_shared((char*)&Asm[st][rr * HS_STR] + kc * 2);
            cp16z(da, A + (size_t)(m0 + rr) * Dd + k0 + kc, (m0 + rr) < M);
        }
        #pragma unroll
        for (int u = 0; u < 4; u++) {
            int rr = r + u * 64;
            uint32_t db = __cvta_generic_to_shared((char*)&Bsm[st][rr * HS_STR] + kc * 2);
            cp16(db, Bm + (size_t)(n0 + rr) * Dd + k0 + kc);
        }
        cp_commit();
    };

    const int NCH = Dd / 32;
    load_stage(0, 0);
    load_stage(1, 32);
    for (int ch = 0; ch < NCH; ch++) {
        if (ch < NCH - 1) cp_wait1(); else cp_wait0();
        __syncthreads();
        if (ch + 2 < NCH) load_stage((ch + 2) % 3, (ch + 2) * 32);
        mma_chunk_h(Asm[ch % 3], Bsm[ch % 3], cacc, wm, wn, g, tg);
    }

    float s0[4] = {}, q0[4] = {}, s1[4] = {}, q1[4] = {};
    #pragma unroll
    for (int mt = 0; mt < 4; mt++) {
        int m = m0 + wm * 64 + mt * 16 + g;
        #pragma unroll
        for (int nt = 0; nt < 8; nt++) {
            int n = n0 + wn * 64 + nt * 8 + tg * 2;
            float2 bb = *(const float2*)(bias + n);
            float2 r0 = make_float2(cacc[mt][nt][0] + bb.x, cacc[mt][nt][1] + bb.y);
            float2 r1 = make_float2(cacc[mt][nt][2] + bb.x, cacc[mt][nt][3] + bb.y);
            if (m < M) *(float2*)(out + (size_t)m * Cch + n) = r0;
            if (m + 8 < M) *(float2*)(out + (size_t)(m + 8) * Cch + n) = r1;
            s0[mt] += r0.x + r0.y; q0[mt] += r0.x * r0.x + r0.y * r0.y;
            s1[mt] += r1.x + r1.y; q1[mt] += r1.x * r1.x + r1.y * r1.y;
        }
    }
    if (blockIdx.z == 0) {
        #pragma unroll
        for (int mt = 0; mt < 4; mt++) {
            int m = m0 + wm * 64 + mt * 16 + g;
            if (m < M) stat_atomic(s0[mt], q0[mt], tg, &g_ksum[m], &g_ksq[m]);
            if (m + 8 < M) stat_atomic(s1[mt], q1[mt], tg, &g_ksum[m + 8], &g_ksq[m + 8]);
        }
    }
}

// ---- Q projection: A = g_xth tokens, B = wq. M=4096, N=512. grid (2, 32, 16). ----
__global__ __launch_bounds__(256, 1) void q_proj_h(const float* __restrict__ bq)
{
    const int b = blockIdx.z;
    const __half* A = g_xth + (size_t)b * HWs * Cch;
    float* out = g_q + (size_t)b * HWs * Cch;

    extern __shared__ uint32_t dsm[];
    uint32_t* Asm[3] = { dsm, dsm + (STAGE_AH + STAGE_BH), dsm + 2 * (STAGE_AH + STAGE_BH) };
    uint32_t* Bsm[3] = { dsm + STAGE_AH, dsm + (STAGE_AH + STAGE_BH) + STAGE_AH,
                         dsm + 2 * (STAGE_AH + STAGE_BH) + STAGE_AH };

    const int m0 = blockIdx.y * 128, n0 = blockIdx.x * 256;
    const int tid = threadIdx.x, lane = tid & 31, wid = tid >> 5;
    const int wm = wid & 1, wn = wid >> 1;
    const int g = lane >> 2, tg = lane & 3;
    const int r = tid >> 2, kc = (tid & 3) * 8;
    float cacc[4][8][4] = {};

    auto load_stage = [&](int st, int k0) {
        #pragma unroll
        for (int u = 0; u < 2; u++) {
            int rr = r + u * 64;
            uint32_t da = __cvta_generic_to_shared((char*)&Asm[st][rr * HS_STR] + kc * 2);
            cp16(da, A + (size_t)(m0 + rr) * Cch + k0 + kc);
        }
        #pragma unroll
        for (int u = 0; u < 4; u++) {
            int rr = r + u * 64;
            uint32_t db = __cvta_generic_to_shared((char*)&Bsm[st][rr * HS_STR] + kc * 2);
            cp16(db, g_wqh + (size_t)(n0 + rr) * Cch + k0 + kc);
        }
        cp_commit();
    };

    const int NCH = Cch / 32;
    load_stage(0, 0);
    load_stage(1, 32);
    for (int ch = 0; ch < NCH; ch++) {
        if (ch < NCH - 1) cp_wait1(); else cp_wait0();
        __syncthreads();
        if (ch + 2 < NCH) load_stage((ch + 2) % 3, (ch + 2) * 32);
        mma_chunk_h(Asm[ch % 3], Bsm[ch % 3], cacc, wm, wn, g, tg);
    }

    const float pes = 0.05f / 63.0f;
    float s0[4] = {}, q0[4] = {}, s1[4] = {}, q1[4] = {};
    #pragma unroll
    for (int mt = 0; mt < 4; mt++) {
        int m = m0 + wm * 64 + mt * 16 + g;
        float pw0x = pes * (float)(m & 63), pw0y = pes * (float)((m >> 6) & 63);
        float pw1x = pes * (float)((m + 8) & 63), pw1y = pes * (float)(((m + 8) >> 6) & 63);
        #pragma unroll
        for (int nt = 0; nt < 8; nt++) {
            int n = n0 + wn * 64 + nt * 8 + tg * 2;
            float2 bb = *(const float2*)(bq + n);
            bool use_x = n < (Cch / 2);
            float pe0 = use_x ? pw0x : pw0y;
            float pe1 = use_x ? pw1x : pw1y;
            float2 r0 = make_float2(cacc[mt][nt][0] + bb.x + pe0, cacc[mt][nt][1] + bb.y + pe0);
            float2 r1 = make_float2(cacc[mt][nt][2] + bb.x + pe1, cacc[mt][nt][3] + bb.y + pe1);
            *(float2*)(out + (size_t)m * Cch + n) = r0;
            *(float2*)(out + (size_t)(m + 8) * Cch + n) = r1;
            s0[mt] += r0.x + r0.y; q0[mt] += r0.x * r0.x + r0.y * r0.y;
            s1[mt] += r1.x + r1.y; q1[mt] += r1.x * r1.x + r1.y * r1.y;
        }
    }
    #pragma unroll
    for (int mt = 0; mt < 4; mt++) {
        int m = m0 + wm * 64 + mt * 16 + g;
        size_t row = (size_t)b * HWs + m;
        stat_atomic(s0[mt], q0[mt], tg, &g_qsum[row], &g_qsq[row]);
        stat_atomic(s1[mt], q1[mt], tg, &g_qsum[row + 8], &g_qsq[row + 8]);
    }
}

// ---- O projection: A = wo, B = g_attnh. M=512, N=4096. grid (16, 4, 16). ----
__global__ __launch_bounds__(256, 1) void o_proj_h(
    const float* __restrict__ bo, const float* __restrict__ x, float* __restrict__ outp)
{
    const int b = blockIdx.z;
    const __half* Bm = g_attnh + (size_t)b * HWs * Cch;

    extern __shared__ uint32_t dsm[];
    uint32_t* Asm[3] = { dsm, dsm + (STAGE_AH + STAGE_BH), dsm + 2 * (STAGE_AH + STAGE_BH) };
    uint32_t* Bsm[3] = { dsm + STAGE_AH, dsm + (STAGE_AH + STAGE_BH) + STAGE_AH,
                         dsm + 2 * (STAGE_AH + STAGE_BH) + STAGE_AH };

    const int m0 = blockIdx.y * 128, n0 = blockIdx.x * 256;
    const int tid = threadIdx.x, lane = tid & 31, wid = tid >> 5;
    const int wm = wid & 1, wn = wid >> 1;
    const int g = lane >> 2, tg = lane & 3;
    const int r = tid >> 2, kc = (tid & 3) * 8;
    float cacc[4][8][4] = {};

    auto load_stage = [&](int st, int k0) {
        #pragma unroll
        for (int u = 0; u < 2; u++) {
            int rr = r + u * 64;
            uint32_t da = __cvta_generic_to_shared((char*)&Asm[st][rr * HS_STR] + kc * 2);
            cp16(da, g_woh + (size_t)(m0 + rr) * Cch + k0 + kc);
        }
        #pragma unroll
        for (int u = 0; u < 4; u++) {
            int rr = r + u * 64;
            uint32_t db = __cvta_generic_to_shared((char*)&Bsm[st][rr * HS_STR] + kc * 2);
            cp16(db, Bm + (size_t)(n0 + rr) * Cch + k0 + kc);
        }
        cp_commit();
    };

    const int NCH = Cch / 32;
    load_stage(0, 0);
    load_stage(1, 32);
    for (int ch = 0; ch < NCH; ch++) {
        if (ch < NCH - 1) cp_wait1(); else cp_wait0();
        __syncthreads();
        if (ch + 2 < NCH) load_stage((ch + 2) % 3, (ch + 2) * 32);
        mma_chunk_h(Asm[ch % 3], Bsm[ch % 3], cacc, wm, wn, g, tg);
    }

    #pragma unroll
    for (int mt = 0; mt < 4; mt++) {
        int m = m0 + wm * 64 + mt * 16 + g;     // channel
        float bo0 = bo[m], bo1 = bo[m + 8];
        #pragma unroll
        for (int nt = 0; nt < 8; nt++) {
            int n = n0 + wn * 64 + nt * 8 + tg * 2; // token
            size_t i0 = (size_t)b * Cch * HWs + (size_t)m * HWs + n;
            size_t i1 = (size_t)b * Cch * HWs + (size_t)(m + 8) * HWs + n;
            float2 x0 = *(const float2*)(x + i0);
            float2 x1 = *(const float2*)(x + i1);
            float2 r0 = make_float2(cacc[mt][nt][0] + bo0 + x0.x, cacc[mt][nt][1] + bo0 + x0.y);
            float2 r1 = make_float2(cacc[mt][nt][2] + bo1 + x1.x, cacc[mt][nt][3] + bo1 + x1.y);
            *(float2*)(outp + i0) = r0;
            *(float2*)(outp + i1) = r1;
        }
    }
}

// =====================================================================
// Apply K LayerNorm in place. grid (Bsz*Lt), 128 thr.
// =====================================================================
__global__ __launch_bounds__(128) void ln_k_apply(
    const float* __restrict__ g2, const float* __restrict__ b2)
{
    int row = blockIdx.x;
    float m = g_ksum[row] * (1.0f / 512.0f);
    float rs = rsqrtf(g_ksq[row] * (1.0f / 512.0f) - m * m + 1e-5f);
    float* p = g_k + (size_t)row * Cch;
    int t = threadIdx.x;
    float4 v = *(float4*)(p + t * 4);
    float4 gg = *(const float4*)(g2 + t * 4);
    float4 bb = *(const float4*)(b2 + t * 4);
    v.x = (v.x - m) * rs * gg.x + bb.x;
    v.y = (v.y - m) * rs * gg.y + bb.y;
    v.z = (v.z - m) * rs * gg.z + bb.z;
    v.w = (v.w - m) * rs * gg.w + bb.w;
    *(float4*)(p + t * 4) = v;
}

// =====================================================================
// Tensor-core attention (tf32 mainloop, unchanged from R13) — output half.
// =====================================================================
#define QS_STR 84
#define KS_STR 68
#define VS_STR 68
#define ATTN_SMEM ((128 * QS_STR + 80 * KS_STR + 80 * VS_STR + 128 + 128) * 4)

__global__ __launch_bounds__(256) void attn_tc(
    const float* __restrict__ g1, const float* __restrict__ b1)
{
    extern __shared__ float sm[];
    float* Qs = sm;
    float* Ks = Qs + 128 * QS_STR;
    float* Vs = Ks + 80 * KS_STR;
    float* qmu = Vs + 80 * VS_STR;
    float* qrs = qmu + 128;

    const int tid = threadIdx.x, lane = tid & 31, w = tid >> 5;
    const int g = lane >> 2, tg = lane & 3;
    const int t0 = blockIdx.x * 128, h = blockIdx.y, b = blockIdx.z;

    if (tid < 128) {
        size_t row = (size_t)b * HWs + t0 + tid;
        float s = g_qsum[row], q = g_qsq[row];
        float m = s * (1.0f / 512.0f);
        qmu[tid] = m;
        qrs[tid] = rsqrtf(q * (1.0f / 512.0f) - m * m + 1e-5f);
    }
    __syncthreads();

    const float* qb = g_q + ((size_t)b * HWs + t0) * Cch + h * HDd;
    for (int f = tid; f < 128 * 16; f += 256) {
        int t = f >> 4, dc = (f & 15) << 2;
        float4 v = *(const float4*)(qb + (size_t)t * Cch + dc);
        float4 gg = *(const float4*)(g1 + h * HDd + dc);
        float4 bb = *(const float4*)(b1 + h * HDd + dc);
        float m = qmu[t], r = qrs[t];
        float* d = Qs + t * QS_STR + dc;
        d[0] = (v.x - m) * r * gg.x + bb.x;
        d[1] = (v.y - m) * r * gg.y + bb.y;
        d[2] = (v.z - m) * r * gg.z + bb.z;
        d[3] = (v.w - m) * r * gg.w + bb.w;
    }
    const float* kb = g_k + (size_t)b * Lt * Cch + h * HDd;
    const float* vb = g_v + (size_t)b * Lt * Cch + h * HDd;
    for (int f = tid; f < 80 * 16; f += 256) {
        int l = f >> 4, dc = (f & 15) << 2;
        float* kd = Ks + l * KS_STR + dc;
        float* vd = Vs + l * VS_STR + dc;
        if (l < Lt) {
            float4 k4 = *(const float4*)(kb + (size_t)l * Cch + dc);
            float4 v4 = *(const float4*)(vb + (size_t)l * Cch + dc);
            kd[0] = k4.x; kd[1] = k4.y; kd[2] = k4.z; kd[3] = k4.w;
            vd[0] = v4.x; vd[1] = v4.y; vd[2] = v4.z; vd[3] = v4.w;
        } else {
            kd[0] = kd[1] = kd[2] = kd[3] = 0.f;
            vd[0] = vd[1] = vd[2] = vd[3] = 0.f;
        }
    }
    __syncthreads();

    const uint32_t* Qu = (const uint32_t*)Qs;
    const uint32_t* Ku = (const uint32_t*)Ks;
    const uint32_t* Vu = (const uint32_t*)Vs;

    float sfr[10][4] = {};
    #pragma unroll
    for (int ks = 0; ks < 8; ks++) {
        uint32_t aq[4];
        int ab = (w * 16 + g) * QS_STR + ks * 8 + tg;
        aq[0] = Qu[ab];
        aq[1] = Qu[ab + 8 * QS_STR];
        aq[2] = Qu[ab + 4];
        aq[3] = Qu[ab + 8 * QS_STR + 4];
        #pragma unroll
        for (int nt = 0; nt < 10; nt++) {
            uint32_t bf[2];
            int bb = (nt * 8 + g) * KS_STR + ks * 8 + tg;
            bf[0] = Ku[bb];
            bf[1] = Ku[bb + 4];
            mma8(sfr[nt], aq, bf);
        }
    }

    float sum0 = 0.f, sum1 = 0.f;
    #pragma unroll
    for (int nt = 0; nt < 10; nt++) {
        int c0 = nt * 8 + tg * 2, c1 = c0 + 1;
        float e00 = (c0 < Lt) ? __expf(sfr[nt][0] * 0.125f) : 0.f;
        float e01 = (c1 < Lt) ? __expf(sfr[nt][1] * 0.125f) : 0.f;
        float e10 = (c0 < Lt) ? __expf(sfr[nt][2] * 0.125f) : 0.f;
        float e11 = (c1 < Lt) ? __expf(sfr[nt][3] * 0.125f) : 0.f;
        sum0 += e00 + e01; sum1 += e10 + e11;
        sfr[nt][0] = e00; sfr[nt][1] = e01; sfr[nt][2] = e10; sfr[nt][3] = e11;
    }
    sum0 += __shfl_xor_sync(0xffffffffu, sum0, 1);
    sum0 += __shfl_xor_sync(0xffffffffu, sum0, 2);
    sum1 += __shfl_xor_sync(0xffffffffu, sum1, 1);
    sum1 += __shfl_xor_sync(0xffffffffu, sum1, 2);
    float inv0 = 1.0f / sum0, inv1 = 1.0f / sum1;

    __syncwarp();
    {
        float* prow0 = Qs + (w * 16 + g) * QS_STR;
        float* prow1 = Qs + (w * 16 + g + 8) * QS_STR;
        #pragma unroll
        for (int nt = 0; nt < 10; nt++) {
            int c0 = nt * 8 + tg * 2;
            *(float2*)(prow0 + c0) = make_float2(sfr[nt][0] * inv0, sfr[nt][1] * inv0);
            *(float2*)(prow1 + c0) = make_float2(sfr[nt][2] * inv1, sfr[nt][3] * inv1);
        }
    }
    __syncwarp();

    float ofr[8][4] = {};
    #pragma unroll
    for (int kt = 0; kt < 10; kt++) {
        uint32_t ap[4];
        int ab = (w * 16 + g) * QS_STR + kt * 8 + tg;
        ap[0] = Qu[ab];
        ap[1] = Qu[ab + 8 * QS_STR];
        ap[2] = Qu[ab + 4];
        ap[3] = Qu[ab + 8 * QS_STR + 4];
        #pragma unroll
        for (int nt = 0; nt < 8; nt++) {
            uint32_t bf[2];
            bf[0] = Vu[(kt * 8 + tg) * VS_STR + nt * 8 + g];
            bf[1] = Vu[(kt * 8 + tg + 4) * VS_STR + nt * 8 + g];
            mma8(ofr[nt], ap, bf);
        }
    }

    __half* ob = g_attnh + ((size_t)b * HWs + t0 + w * 16) * Cch + h * HDd;
    #pragma unroll
    for (int nt = 0; nt < 8; nt++) {
        int n = nt * 8 + tg * 2;
        *(__half2*)(ob + (size_t)g * Cch + n) = __floats2half2_rn(ofr[nt][0], ofr[nt][1]);
        *(__half2*)(ob + (size_t)(g + 8) * Cch + n) = __floats2half2_rn(ofr[nt][2], ofr[nt][3]);
    }
}

// =====================================================================
extern "C" void kernel_launch(void* const* d_in, const int* in_sizes, int n_in,
                              void* d_out, int out_size)
{
    const float* x  = (const float*)d_in[0];
    const float* tf = (const float*)d_in[1];
    const float* wq = (const float*)d_in[2];
    const float* bq = (const float*)d_in[3];
    const float* wk = (const float*)d_in[4];
    const float* bk = (const float*)d_in[5];
    const float* wv = (const float*)d_in[6];
    const float* bv = (const float*)d_in[7];
    const float* wo = (const float*)d_in[8];
    const float* bo = (const float*)d_in[9];
    const float* g1 = (const float*)d_in[10];
    const float* b1 = (const float*)d_in[11];
    const float* g2 = (const float*)d_in[12];
    const float* b2 = (const float*)d_in[13];
    float* out = (float*)d_out;

    cudaFuncSetAttribute(kv_proj_h, cudaFuncAttributeMaxDynamicSharedMemorySize, GEMM_SMEM);
    cudaFuncSetAttribute(q_proj_h, cudaFuncAttributeMaxDynamicSharedMemorySize, GEMM_SMEM);
    cudaFuncSetAttribute(o_proj_h, cudaFuncAttributeMaxDynamicSharedMemorySize, GEMM_SMEM);
    cudaFuncSetAttribute(attn_tc, cudaFuncAttributeMaxDynamicSharedMemorySize, ATTN_SMEM);

    zero_stats_kernel<<<(Bsz * HWs + 255) / 256, 256>>>();
    convert_params_kernel<<<(NQ_TOTAL + 255) / 256, 256>>>(wq, wk, wv, wo, tf);
    xpose_kernel<<<dim3(HWs / 32, Cch / 32, Bsz), 256>>>(x);
    kv_proj_h<<<dim3(2, 10, 2), 256, GEMM_SMEM>>>(bk, bv);
    ln_k_apply<<<Bsz * Lt, 128>>>(g2, b2);
    q_proj_h<<<dim3(2, 32, 16), 256, GEMM_SMEM>>>(bq);
    attn_tc<<<dim3(32, 8, 16), 256, ATTN_SMEM>>>(g1, b1);
    o_proj_h<<<dim3(16, 4, 16), 256, GEMM_SMEM>>>(bo, x, out);
}

// round 17
// speedup vs baseline: 1.3448x; 1.0815x over previous
#include <cuda_runtime.h>
#include <cuda_fp16.h>
#include <cstdint>

#define Bsz 16
#define Cch 512
#define HWs 4096
#define Lt  77
#define Dd  768
#define NHh 8
#define HDd 64

// ---------------- scratch ----------------
__device__ float g_k[Bsz * Lt * Cch];
__device__ float g_v[Bsz * Lt * Cch];
__device__ float g_qsum[Bsz * HWs];
__device__ float g_qsq[Bsz * HWs];
__device__ float g_ksum[Bsz * Lt];
__device__ float g_ksq[Bsz * Lt];
__device__ __half g_qh[(size_t)Bsz * HWs * Cch];     // q proj out (half, pre-LN)
__device__ __half g_xth[(size_t)Bsz * HWs * Cch];    // x transposed [b][hw][c]
__device__ __half g_attnh[(size_t)Bsz * HWs * Cch];  // attention out (half)
__device__ __half g_wqh[Cch * Cch];
__device__ __half g_wkh[Cch * Dd];
__device__ __half g_wvh[Cch * Dd];
__device__ __half g_woh[Cch * Cch];
__device__ __half g_tfh[Bsz * Lt * Dd];

// =====================================================================
// helpers
// =====================================================================
__device__ __forceinline__ void mma16(float* c, const uint32_t* a, const uint32_t* b) {
    asm volatile(
        "mma.sync.aligned.m16n8k16.row.col.f32.f16.f16.f32 "
        "{%0,%1,%2,%3}, {%4,%5,%6,%7}, {%8,%9}, {%0,%1,%2,%3};"
        : "+f"(c[0]), "+f"(c[1]), "+f"(c[2]), "+f"(c[3])
        : "r"(a[0]), "r"(a[1]), "r"(a[2]), "r"(a[3]), "r"(b[0]), "r"(b[1]));
}

__device__ __forceinline__ void cp16(uint32_t dst, const void* src) {
    asm volatile("cp.async.cg.shared.global [%0], [%1], 16;" :: "r"(dst), "l"(src));
}
__device__ __forceinline__ void cp16z(uint32_t dst, const void* src, bool pred) {
    int sz = pred ? 16 : 0;
    asm volatile("cp.async.cg.shared.global [%0], [%1], 16, %2;" :: "r"(dst), "l"(src), "r"(sz));
}
__device__ __forceinline__ void cp_commit() { asm volatile("cp.async.commit_group;"); }
__device__ __forceinline__ void cp_wait1() { asm volatile("cp.async.wait_group 1;"); }
__device__ __forceinline__ void cp_wait0() { asm volatile("cp.async.wait_group 0;"); }

#define HS_STR 28                 // GEMM smem row stride in u32 (56 halfs)
#define STAGE_AH (128 * HS_STR)
#define STAGE_BH (256 * HS_STR)
#define STAGE_AH64 (64 * HS_STR)

// ---- fp16 chunk: 128x256 tile, warp 64x64, k-chunk 32 ----
__device__ __forceinline__ void mma_chunk_h(
    const uint32_t* __restrict__ As, const uint32_t* __restrict__ Bs,
    float cacc[4][8][4], int wm, int wn, int g, int tg)
{
    #pragma unroll
    for (int ks = 0; ks < 2; ks++) {
        uint32_t af[4][4], bf[8][2];
        #pragma unroll
        for (int mt = 0; mt < 4; mt++) {
            int base = (wm * 64 + mt * 16 + g) * HS_STR + ks * 8 + tg;
            af[mt][0] = As[base];
            af[mt][1] = As[base + 8 * HS_STR];
            af[mt][2] = As[base + 4];
            af[mt][3] = As[base + 8 * HS_STR + 4];
        }
        #pragma unroll
        for (int nt = 0; nt < 8; nt++) {
            int bb = (wn * 64 + nt * 8 + g) * HS_STR + ks * 8 + tg;
            bf[nt][0] = Bs[bb];
            bf[nt][1] = Bs[bb + 4];
        }
        #pragma unroll
        for (int mt = 0; mt < 4; mt++)
            #pragma unroll
            for (int nt = 0; nt < 8; nt++)
                mma16(cacc[mt][nt], af[mt], bf[nt]);
    }
}

// ---- fp16 chunk: 64x256 tile (kv), warp 32x64 ----
__device__ __forceinline__ void mma_chunk_h64(
    const uint32_t* __restrict__ As, const uint32_t* __restrict__ Bs,
    float cacc[2][8][4], int wm, int wn, int g, int tg)
{
    #pragma unroll
    for (int ks = 0; ks < 2; ks++) {
        uint32_t af[2][4], bf[8][2];
        #pragma unroll
        for (int mt = 0; mt < 2; mt++) {
            int base = (wm * 32 + mt * 16 + g) * HS_STR + ks * 8 + tg;
            af[mt][0] = As[base];
            af[mt][1] = As[base + 8 * HS_STR];
            af[mt][2] = As[base + 4];
            af[mt][3] = As[base + 8 * HS_STR + 4];
        }
        #pragma unroll
        for (int nt = 0; nt < 8; nt++) {
            int bb = (wn * 64 + nt * 8 + g) * HS_STR + ks * 8 + tg;
            bf[nt][0] = Bs[bb];
            bf[nt][1] = Bs[bb + 4];
        }
        #pragma unroll
        for (int mt = 0; mt < 2; mt++)
            #pragma unroll
            for (int nt = 0; nt < 8; nt++)
                mma16(cacc[mt][nt], af[mt], bf[nt]);
    }
}

__device__ __forceinline__ void stat_atomic(float s, float q, int tg, float* sumA, float* sqA) {
    s += __shfl_xor_sync(0xffffffffu, s, 1);
    s += __shfl_xor_sync(0xffffffffu, s, 2);
    q += __shfl_xor_sync(0xffffffffu, q, 1);
    q += __shfl_xor_sync(0xffffffffu, q, 2);
    if (tg == 0) { atomicAdd(sumA, s); atomicAdd(sqA, q); }
}

// =====================================================================
__global__ void zero_stats_kernel() {
    int i = blockIdx.x * 256 + threadIdx.x;
    if (i < Bsz * HWs) { g_qsum[i] = 0.f; g_qsq[i] = 0.f; }
    if (i < Bsz * Lt) { g_ksum[i] = 0.f; g_ksq[i] = 0.f; }
}

// =====================================================================
// convert params fp32 -> fp16
// =====================================================================
#define NQ_WQ (Cch * Cch / 4)
#define NQ_WK (Cch * Dd / 4)
#define NQ_WO (Cch * Cch / 4)
#define NQ_TF (Bsz * Lt * Dd / 4)
#define NQ_TOTAL (NQ_WQ + NQ_WK + NQ_WK + NQ_WO + NQ_TF)

__global__ __launch_bounds__(256) void convert_params_kernel(
    const float* __restrict__ wq, const float* __restrict__ wk,
    const float* __restrict__ wv, const float* __restrict__ wo,
    const float* __restrict__ tf)
{
    int idx = blockIdx.x * 256 + threadIdx.x;
    if (idx >= NQ_TOTAL) return;
    const float* src; __half* dst;
    if (idx < NQ_WQ) { src = wq; dst = g_wqh; }
    else if ((idx -= NQ_WQ) < NQ_WK) { src = wk; dst = g_wkh; }
    else if ((idx -= NQ_WK) < NQ_WK) { src = wv; dst = g_wvh; }
    else if ((idx -= NQ_WK) < NQ_WO) { src = wo; dst = g_woh; }
    else { idx -= NQ_WO; src = tf; dst = g_tfh; }
    float4 v = *(const float4*)(src + (size_t)idx * 4);
    *(__half2*)(dst + (size_t)idx * 4) = __floats2half2_rn(v.x, v.y);
    *(__half2*)(dst + (size_t)idx * 4 + 2) = __floats2half2_rn(v.z, v.w);
}

// =====================================================================
// transpose-convert x: [b][c][hw] f32 -> g_xth [b][hw][c] half
// =====================================================================
__global__ __launch_bounds__(256) void xpose_kernel(const float* __restrict__ x)
{
    __shared__ float ts[32][33];
    const int hw0 = blockIdx.x * 32, c0 = blockIdx.y * 32, b = blockIdx.z;
    const int tx = threadIdx.x & 31, ty = threadIdx.x >> 5;
    const float* xb = x + (size_t)b * Cch * HWs;
    #pragma unroll
    for (int i = 0; i < 4; i++) {
        int c = ty * 4 + i;
        ts[c][tx] = xb[(size_t)(c0 + c) * HWs + hw0 + tx];
    }
    __syncthreads();
    __half* ob = g_xth + (size_t)b * HWs * Cch;
    const int tx2 = threadIdx.x & 15, tr = threadIdx.x >> 4;
    #pragma unroll
    for (int i = 0; i < 2; i++) {
        int r = tr + i * 16;
        __half2 h = __floats2half2_rn(ts[tx2 * 2][r], ts[tx2 * 2 + 1][r]);
        *(__half2*)(ob + (size_t)(hw0 + r) * Cch + c0 + tx2 * 2) = h;
    }
}

#define GEMM_SMEM (3 * (STAGE_AH + STAGE_BH) * 4)
#define KV_SMEM (3 * (STAGE_AH64 + STAGE_BH) * 4)

// =====================================================================
// KV projection: 64m x 256n tile, warp 32x64. M=1232, N=512, K=768.
// grid (2, 20, 2) z: 0->k (+stats), 1->v.
// =====================================================================
__global__ __launch_bounds__(256, 2) void kv_proj_h(
    const float* __restrict__ bk, const float* __restrict__ bv)
{
    const int M = Bsz * Lt;
    const __half* A = g_tfh;
    const __half* Bm; const float* bias; float* out;
    if (blockIdx.z == 0) { Bm = g_wkh; bias = bk; out = g_k; }
    else                 { Bm = g_wvh; bias = bv; out = g_v; }

    extern __shared__ uint32_t dsm[];
    uint32_t* Asm[3] = { dsm, dsm + (STAGE_AH64 + STAGE_BH), dsm + 2 * (STAGE_AH64 + STAGE_BH) };
    uint32_t* Bsm[3] = { dsm + STAGE_AH64, dsm + (STAGE_AH64 + STAGE_BH) + STAGE_AH64,
                         dsm + 2 * (STAGE_AH64 + STAGE_BH) + STAGE_AH64 };

    const int m0 = blockIdx.y * 64, n0 = blockIdx.x * 256;
    const int tid = threadIdx.x, lane = tid & 31, wid = tid >> 5;
    const int wm = wid & 1, wn = wid >> 1;
    const int g = lane >> 2, tg = lane & 3;
    const int r = tid >> 2, kc = (tid & 3) * 8;
    float cacc[2][8][4] = {};

    auto load_stage = [&](int st, int k0) {
        {
            uint32_t da = __cvta_generic_to_shared((char*)&Asm[st][r * HS_STR] + kc * 2);
            cp16z(da, A + (size_t)(m0 + r) * Dd + k0 + kc, (m0 + r) < M);
        }
        #pragma unroll
        for (int u = 0; u < 4; u++) {
            int rr = r + u * 64;
            uint32_t db = __cvta_generic_to_shared((char*)&Bsm[st][rr * HS_STR] + kc * 2);
            cp16(db, Bm + (size_t)(n0 + rr) * Dd + k0 + kc);
        }
        cp_commit();
    };

    const int NCH = Dd / 32;
    load_stage(0, 0);
    load_stage(1, 32);
    for (int ch = 0; ch < NCH; ch++) {
        if (ch < NCH - 1) cp_wait1(); else cp_wait0();
        __syncthreads();
        if (ch + 2 < NCH) load_stage((ch + 2) % 3, (ch + 2) * 32);
        mma_chunk_h64(Asm[ch % 3], Bsm[ch % 3], cacc, wm, wn, g, tg);
    }

    float s0[2] = {}, q0[2] = {}, s1[2] = {}, q1[2] = {};
    #pragma unroll
    for (int mt = 0; mt < 2; mt++) {
        int m = m0 + wm * 32 + mt * 16 + g;
        #pragma unroll
        for (int nt = 0; nt < 8; nt++) {
            int n = n0 + wn * 64 + nt * 8 + tg * 2;
            float2 bb = *(const float2*)(bias + n);
            float2 r0 = make_float2(cacc[mt][nt][0] + bb.x, cacc[mt][nt][1] + bb.y);
            float2 r1 = make_float2(cacc[mt][nt][2] + bb.x, cacc[mt][nt][3] + bb.y);
            if (m < M) *(float2*)(out + (size_t)m * Cch + n) = r0;
            if (m + 8 < M) *(float2*)(out + (size_t)(m + 8) * Cch + n) = r1;
            s0[mt] += r0.x + r0.y; q0[mt] += r0.x * r0.x + r0.y * r0.y;
            s1[mt] += r1.x + r1.y; q1[mt] += r1.x * r1.x + r1.y * r1.y;
        }
    }
    if (blockIdx.z == 0) {
        #pragma unroll
        for (int mt = 0; mt < 2; mt++) {
            int m = m0 + wm * 32 + mt * 16 + g;
            if (m < M) stat_atomic(s0[mt], q0[mt], tg, &g_ksum[m], &g_ksq[m]);
            if (m + 8 < M) stat_atomic(s1[mt], q1[mt], tg, &g_ksum[m + 8], &g_ksq[m + 8]);
        }
    }
}

// =====================================================================
// Q projection: writes g_qh (half) + LN stats. M=4096, N=512. grid (2, 32, 16).
// =====================================================================
__global__ __launch_bounds__(256, 1) void q_proj_h(const float* __restrict__ bq)
{
    const int b = blockIdx.z;
    const __half* A = g_xth + (size_t)b * HWs * Cch;
    __half* out = g_qh + (size_t)b * HWs * Cch;

    extern __shared__ uint32_t dsm[];
    uint32_t* Asm[3] = { dsm, dsm + (STAGE_AH + STAGE_BH), dsm + 2 * (STAGE_AH + STAGE_BH) };
    uint32_t* Bsm[3] = { dsm + STAGE_AH, dsm + (STAGE_AH + STAGE_BH) + STAGE_AH,
                         dsm + 2 * (STAGE_AH + STAGE_BH) + STAGE_AH };

    const int m0 = blockIdx.y * 128, n0 = blockIdx.x * 256;
    const int tid = threadIdx.x, lane = tid & 31, wid = tid >> 5;
    const int wm = wid & 1, wn = wid >> 1;
    const int g = lane >> 2, tg = lane & 3;
    const int r = tid >> 2, kc = (tid & 3) * 8;
    float cacc[4][8][4] = {};

    auto load_stage = [&](int st, int k0) {
        #pragma unroll
        for (int u = 0; u < 2; u++) {
            int rr = r + u * 64;
            uint32_t da = __cvta_generic_to_shared((char*)&Asm[st][rr * HS_STR] + kc * 2);
            cp16(da, A + (size_t)(m0 + rr) * Cch + k0 + kc);
        }
        #pragma unroll
        for (int u = 0; u < 4; u++) {
            int rr = r + u * 64;
            uint32_t db = __cvta_generic_to_shared((char*)&Bsm[st][rr * HS_STR] + kc * 2);
            cp16(db, g_wqh + (size_t)(n0 + rr) * Cch + k0 + kc);
        }
        cp_commit();
    };

    const int NCH = Cch / 32;
    load_stage(0, 0);
    load_stage(1, 32);
    for (int ch = 0; ch < NCH; ch++) {
        if (ch < NCH - 1) cp_wait1(); else cp_wait0();
        __syncthreads();
        if (ch + 2 < NCH) load_stage((ch + 2) % 3, (ch + 2) * 32);
        mma_chunk_h(Asm[ch % 3], Bsm[ch % 3], cacc, wm, wn, g, tg);
    }

    const float pes = 0.05f / 63.0f;
    float s0[4] = {}, q0[4] = {}, s1[4] = {}, q1[4] = {};
    #pragma unroll
    for (int mt = 0; mt < 4; mt++) {
        int m = m0 + wm * 64 + mt * 16 + g;
        float pw0x = pes * (float)(m & 63), pw0y = pes * (float)((m >> 6) & 63);
        float pw1x = pes * (float)((m + 8) & 63), pw1y = pes * (float)(((m + 8) >> 6) & 63);
        #pragma unroll
        for (int nt = 0; nt < 8; nt++) {
            int n = n0 + wn * 64 + nt * 8 + tg * 2;
            float2 bb = *(const float2*)(bq + n);
            bool use_x = n < (Cch / 2);
            float pe0 = use_x ? pw0x : pw0y;
            float pe1 = use_x ? pw1x : pw1y;
            float2 r0 = make_float2(cacc[mt][nt][0] + bb.x + pe0, cacc[mt][nt][1] + bb.y + pe0);
            float2 r1 = make_float2(cacc[mt][nt][2] + bb.x + pe1, cacc[mt][nt][3] + bb.y + pe1);
            *(__half2*)(out + (size_t)m * Cch + n) = __floats2half2_rn(r0.x, r0.y);
            *(__half2*)(out + (size_t)(m + 8) * Cch + n) = __floats2half2_rn(r1.x, r1.y);
            s0[mt] += r0.x + r0.y; q0[mt] += r0.x * r0.x + r0.y * r0.y;
            s1[mt] += r1.x + r1.y; q1[mt] += r1.x * r1.x + r1.y * r1.y;
        }
    }
    #pragma unroll
    for (int mt = 0; mt < 4; mt++) {
        int m = m0 + wm * 64 + mt * 16 + g;
        size_t row = (size_t)b * HWs + m;
        stat_atomic(s0[mt], q0[mt], tg, &g_qsum[row], &g_qsq[row]);
        stat_atomic(s1[mt], q1[mt], tg, &g_qsum[row + 8], &g_qsq[row + 8]);
    }
}

// =====================================================================
// O projection + bias + residual. M=512, N=4096. grid (16, 4, 16).
// =====================================================================
__global__ __launch_bounds__(256, 1) void o_proj_h(
    const float* __restrict__ bo, const float* __restrict__ x, float* __restrict__ outp)
{
    const int b = blockIdx.z;
    const __half* Bm = g_attnh + (size_t)b * HWs * Cch;

    extern __shared__ uint32_t dsm[];
    uint32_t* Asm[3] = { dsm, dsm + (STAGE_AH + STAGE_BH), dsm + 2 * (STAGE_AH + STAGE_BH) };
    uint32_t* Bsm[3] = { dsm + STAGE_AH, dsm + (STAGE_AH + STAGE_BH) + STAGE_AH,
                         dsm + 2 * (STAGE_AH + STAGE_BH) + STAGE_AH };

    const int m0 = blockIdx.y * 128, n0 = blockIdx.x * 256;
    const int tid = threadIdx.x, lane = tid & 31, wid = tid >> 5;
    const int wm = wid & 1, wn = wid >> 1;
    const int g = lane >> 2, tg = lane & 3;
    const int r = tid >> 2, kc = (tid & 3) * 8;
    float cacc[4][8][4] = {};

    auto load_stage = [&](int st, int k0) {
        #pragma unroll
        for (int u = 0; u < 2; u++) {
            int rr = r + u * 64;
            uint32_t da = __cvta_generic_to_shared((char*)&Asm[st][rr * HS_STR] + kc * 2);
            cp16(da, g_woh + (size_t)(m0 + rr) * Cch + k0 + kc);
        }
        #pragma unroll
        for (int u = 0; u < 4; u++) {
            int rr = r + u * 64;
            uint32_t db = __cvta_generic_to_shared((char*)&Bsm[st][rr * HS_STR] + kc * 2);
            cp16(db, Bm + (size_t)(n0 + rr) * Cch + k0 + kc);
        }
        cp_commit();
    };

    const int NCH = Cch / 32;
    load_stage(0, 0);
    load_stage(1, 32);
    for (int ch = 0; ch < NCH; ch++) {
        if (ch < NCH - 1) cp_wait1(); else cp_wait0();
        __syncthreads();
        if (ch + 2 < NCH) load_stage((ch + 2) % 3, (ch + 2) * 32);
        mma_chunk_h(Asm[ch % 3], Bsm[ch % 3], cacc, wm, wn, g, tg);
    }

    #pragma unroll
    for (int mt = 0; mt < 4; mt++) {
        int m = m0 + wm * 64 + mt * 16 + g;
        float bo0 = bo[m], bo1 = bo[m + 8];
        #pragma unroll
        for (int nt = 0; nt < 8; nt++) {
            int n = n0 + wn * 64 + nt * 8 + tg * 2;
            size_t i0 = (size_t)b * Cch * HWs + (size_t)m * HWs + n;
            size_t i1 = (size_t)b * Cch * HWs + (size_t)(m + 8) * HWs + n;
            float2 x0 = *(const float2*)(x + i0);
            float2 x1 = *(const float2*)(x + i1);
            float2 r0 = make_float2(cacc[mt][nt][0] + bo0 + x0.x, cacc[mt][nt][1] + bo0 + x0.y);
            float2 r1 = make_float2(cacc[mt][nt][2] + bo1 + x1.x, cacc[mt][nt][3] + bo1 + x1.y);
            *(float2*)(outp + i0) = r0;
            *(float2*)(outp + i1) = r1;
        }
    }
}

// =====================================================================
// Apply K LayerNorm in place. grid (Bsz*Lt), 128 thr.
// =====================================================================
__global__ __launch_bounds__(128) void ln_k_apply(
    const float* __restrict__ g2, const float* __restrict__ b2)
{
    int row = blockIdx.x;
    float m = g_ksum[row] * (1.0f / 512.0f);
    float rs = rsqrtf(g_ksq[row] * (1.0f / 512.0f) - m * m + 1e-5f);
    float* p = g_k + (size_t)row * Cch;
    int t = threadIdx.x;
    float4 v = *(float4*)(p + t * 4);
    float4 gg = *(const float4*)(g2 + t * 4);
    float4 bb = *(const float4*)(b2 + t * 4);
    v.x = (v.x - m) * rs * gg.x + bb.x;
    v.y = (v.y - m) * rs * gg.y + bb.y;
    v.z = (v.z - m) * rs * gg.z + bb.z;
    v.w = (v.w - m) * rs * gg.w + bb.w;
    *(float4*)(p + t * 4) = v;
}

// =====================================================================
// fp16 tensor-core attention. LN(Q) fused at load; K pre-normalized; V
// transposed into smem for the PV B operand. P staged through Qs rows (half).
// block = 128 q tokens x head x batch. grid (32, 8, 16), 256 threads.
// =====================================================================
#define QH_STR 44     // u32 stride (88 halfs): holds Q (64) then P (80); banks 12g+tg
#define KH_STR 36     // u32 stride (72 halfs) for K rows; banks 4g+tg
#define VH_STR 44     // u32 stride (88 halfs) for V^T rows (d-major, 80 l cols)
#define ATTN_SMEM ((128 * QH_STR + 80 * KH_STR + 64 * VH_STR) * 4 + 256 * 4)

__global__ __launch_bounds__(256, 2) void attn_h(
    const float* __restrict__ g1, const float* __restrict__ b1)
{
    extern __shared__ uint32_t asm_u[];
    uint32_t* Qu = asm_u;                       // [128][44]
    uint32_t* Ku = Qu + 128 * QH_STR;           // [80][36]
    uint32_t* Vtu = Ku + 80 * KH_STR;           // [64][44]
    float* qmu = (float*)(Vtu + 64 * VH_STR);   // [128]
    float* qrs = qmu + 128;                     // [128]
    __half* Qh = (__half*)Qu;
    __half* Kh = (__half*)Ku;
    __half* Vth = (__half*)Vtu;

    const int tid = threadIdx.x, lane = tid & 31, w = tid >> 5;
    const int g = lane >> 2, tg = lane & 3;
    const int t0 = blockIdx.x * 128, h = blockIdx.y, b = blockIdx.z;

    if (tid < 128) {
        size_t row = (size_t)b * HWs + t0 + tid;
        float s = g_qsum[row], q = g_qsq[row];
        float m = s * (1.0f / 512.0f);
        qmu[tid] = m;
        qrs[tid] = rsqrtf(q * (1.0f / 512.0f) - m * m + 1e-5f);
    }
    __syncthreads();

    // Q: g_qh half -> LN -> half into Qs
    const __half* qb = g_qh + ((size_t)b * HWs + t0) * Cch + h * HDd;
    for (int f = tid; f < 128 * 16; f += 256) {
        int t = f >> 4, dc = (f & 15) << 2;
        __half2 v0 = *(const __half2*)(qb + (size_t)t * Cch + dc);
        __half2 v1 = *(const __half2*)(qb + (size_t)t * Cch + dc + 2);
        float4 gg = *(const float4*)(g1 + h * HDd + dc);
        float4 bb = *(const float4*)(b1 + h * HDd + dc);
        float m = qmu[t], r = qrs[t];
        float q0 = (__half2float(v0.x) - m) * r * gg.x + bb.x;
        float q1 = (__half2float(v0.y) - m) * r * gg.y + bb.y;
        float q2 = (__half2float(v1.x) - m) * r * gg.z + bb.z;
        float q3 = (__half2float(v1.y) - m) * r * gg.w + bb.w;
        __half* d = Qh + t * (QH_STR * 2) + dc;
        *(__half2*)(d) = __floats2half2_rn(q0, q1);
        *(__half2*)(d + 2) = __floats2half2_rn(q2, q3);
    }
    // K rows (pre-LN'd fp32 -> half), V transposed
    const float* kb = g_k + (size_t)b * Lt * Cch + h * HDd;
    const float* vb = g_v + (size_t)b * Lt * Cch + h * HDd;
    for (int f = tid; f < 80 * 16; f += 256) {
        int l = f >> 4, dc = (f & 15) << 2;
        __half* kd = Kh + l * (KH_STR * 2) + dc;
        if (l < Lt) {
            float4 k4 = *(const float4*)(kb + (size_t)l * Cch + dc);
            float4 v4 = *(const float4*)(vb + (size_t)l * Cch + dc);
            *(__half2*)(kd) = __floats2half2_rn(k4.x, k4.y);
            *(__half2*)(kd + 2) = __floats2half2_rn(k4.z, k4.w);
            Vth[(dc + 0) * (VH_STR * 2) + l] = __float2half_rn(v4.x);
            Vth[(dc + 1) * (VH_STR * 2) + l] = __float2half_rn(v4.y);
            Vth[(dc + 2) * (VH_STR * 2) + l] = __float2half_rn(v4.z);
            Vth[(dc + 3) * (VH_STR * 2) + l] = __float2half_rn(v4.w);
        } else {
            *(__half2*)(kd) = __floats2half2_rn(0.f, 0.f);
            *(__half2*)(kd + 2) = __floats2half2_rn(0.f, 0.f);
            Vth[(dc + 0) * (VH_STR * 2) + l] = __float2half_rn(0.f);
            Vth[(dc + 1) * (VH_STR * 2) + l] = __float2half_rn(0.f);
            Vth[(dc + 2) * (VH_STR * 2) + l] = __float2half_rn(0.f);
            Vth[(dc + 3) * (VH_STR * 2) + l] = __float2half_rn(0.f);
        }
    }
    __syncthreads();

    // ---- S = Q K^T: K=64 -> 4 k16 steps, 10 key tiles
    float sfr[10][4] = {};
    #pragma unroll
    for (int ks = 0; ks < 4; ks++) {
        uint32_t aq[4];
        int ab = (w * 16 + g) * QH_STR + ks * 8 + tg;
        aq[0] = Qu[ab];
        aq[1] = Qu[ab + 8 * QH_STR];
        aq[2] = Qu[ab + 4];
        aq[3] = Qu[ab + 8 * QH_STR + 4];
        #pragma unroll
        for (int nt = 0; nt < 10; nt++) {
            uint32_t bf[2];
            int bb = (nt * 8 + g) * KH_STR + ks * 8 + tg;
            bf[0] = Ku[bb];
            bf[1] = Ku[bb + 4];
            mma16(sfr[nt], aq, bf);
        }
    }

    // ---- softmax (no max-subtraction; LN-bounded)
    float sum0 = 0.f, sum1 = 0.f;
    #pragma unroll
    for (int nt = 0; nt < 10; nt++) {
        int c0 = nt * 8 + tg * 2, c1 = c0 + 1;
        float e00 = (c0 < Lt) ? __expf(sfr[nt][0] * 0.125f) : 0.f;
        float e01 = (c1 < Lt) ? __expf(sfr[nt][1] * 0.125f) : 0.f;
        float e10 = (c0 < Lt) ? __expf(sfr[nt][2] * 0.125f) : 0.f;
        float e11 = (c1 < Lt) ? __expf(sfr[nt][3] * 0.125f) : 0.f;
        sum0 += e00 + e01; sum1 += e10 + e11;
        sfr[nt][0] = e00; sfr[nt][1] = e01; sfr[nt][2] = e10; sfr[nt][3] = e11;
    }
    sum0 += __shfl_xor_sync(0xffffffffu, sum0, 1);
    sum0 += __shfl_xor_sync(0xffffffffu, sum0, 2);
    sum1 += __shfl_xor_sync(0xffffffffu, sum1, 1);
    sum1 += __shfl_xor_sync(0xffffffffu, sum1, 2);
    float inv0 = 1.0f / sum0, inv1 = 1.0f / sum1;

    // ---- P (normalized, half) into warp-private Qs rows
    __syncwarp();
    {
        uint32_t* prow0 = Qu + (w * 16 + g) * QH_STR;
        uint32_t* prow1 = Qu + (w * 16 + g + 8) * QH_STR;
        #pragma unroll
        for (int nt = 0; nt < 10; nt++) {
            int cu = nt * 4 + tg;    // u32 col = (nt*8 + tg*2)/2
            __half2 p0 = __floats2half2_rn(sfr[nt][0] * inv0, sfr[nt][1] * inv0);
            __half2 p1 = __floats2half2_rn(sfr[nt][2] * inv1, sfr[nt][3] * inv1);
            prow0[cu] = *(uint32_t*)&p0;
            prow1[cu] = *(uint32_t*)&p1;
        }
    }
    __syncwarp();

    // ---- O = P V: K=80 -> 5 k16 steps, 8 d tiles
    float ofr[8][4] = {};
    #pragma unroll
    for (int ks = 0; ks < 5; ks++) {
        uint32_t ap[4];
        int ab = (w * 16 + g) * QH_STR + ks * 8 + tg;
        ap[0] = Qu[ab];
        ap[1] = Qu[ab + 8 * QH_STR];
        ap[2] = Qu[ab + 4];
        ap[3] = Qu[ab + 8 * QH_STR + 4];
        #pragma unroll
        for (int nt = 0; nt < 8; nt++) {
            uint32_t bf[2];
            int bb = (nt * 8 + g) * VH_STR + ks * 8 + tg;
            bf[0] = Vtu[bb];
            bf[1] = Vtu[bb + 4];
            mma16(ofr[nt], ap, bf);
        }
    }

    __half* ob = g_attnh + ((size_t)b * HWs + t0 + w * 16) * Cch + h * HDd;
    #pragma unroll
    for (int nt = 0; nt < 8; nt++) {
        int n = nt * 8 + tg * 2;
        *(__half2*)(ob + (size_t)g * Cch + n) = __floats2half2_rn(ofr[nt][0], ofr[nt][1]);
        *(__half2*)(ob + (size_t)(g + 8) * Cch + n) = __floats2half2_rn(ofr[nt][2], ofr[nt][3]);
    }
}

// =====================================================================
extern "C" void kernel_launch(void* const* d_in, const int* in_sizes, int n_in,
                              void* d_out, int out_size)
{
    const float* x  = (const float*)d_in[0];
    const float* tf = (const float*)d_in[1];
    const float* wq = (const float*)d_in[2];
    const float* bq = (const float*)d_in[3];
    const float* wk = (const float*)d_in[4];
    const float* bk = (const float*)d_in[5];
    const float* wv = (const float*)d_in[6];
    const float* bv = (const float*)d_in[7];
    const float* wo = (const float*)d_in[8];
    const float* bo = (const float*)d_in[9];
    const float* g1 = (const float*)d_in[10];
    const float* b1 = (const float*)d_in[11];
    const float* g2 = (const float*)d_in[12];
    const float* b2 = (const float*)d_in[13];
    float* out = (float*)d_out;

    cudaFuncSetAttribute(kv_proj_h, cudaFuncAttributeMaxDynamicSharedMemorySize, KV_SMEM);
    cudaFuncSetAttribute(q_proj_h, cudaFuncAttributeMaxDynamicSharedMemorySize, GEMM_SMEM);
    cudaFuncSetAttribute(o_proj_h, cudaFuncAttributeMaxDynamicSharedMemorySize, GEMM_SMEM);
    cudaFuncSetAttribute(attn_h, cudaFuncAttributeMaxDynamicSharedMemorySize, ATTN_SMEM);

    zero_stats_kernel<<<(Bsz * HWs + 255) / 256, 256>>>();
    convert_params_kernel<<<(NQ_TOTAL + 255) / 256, 256>>>(wq, wk, wv, wo, tf);
    xpose_kernel<<<dim3(HWs / 32, Cch / 32, Bsz), 256>>>(x);
    kv_proj_h<<<dim3(2, 20, 2), 256, KV_SMEM>>>(bk, bv);
    ln_k_apply<<<Bsz * Lt, 128>>>(g2, b2);
    q_proj_h<<<dim3(2, 32, 16), 256, GEMM_SMEM>>>(bq);
    attn_h<<<dim3(32, 8, 16), 256, ATTN_SMEM>>>(g1, b1);
    o_proj_h<<<dim3(16, 4, 16), 256, GEMM_SMEM>>>(bo, x, out);
}